// round 9
// baseline (speedup 1.0000x reference)
#include <cuda_runtime.h>
#include <cuda_fp16.h>
#include <cstdint>

// ===================== problem dims =====================
static constexpr int BATCH    = 16384;
static constexpr int DGPE_IN  = 1536;
static constexpr int DGPE_OUT = 1536;
static constexpr int DGPI_IN  = 3072;
static constexpr int DGPI_OUT = 1536;
static constexpr int U3       = 512;
static constexpr int ACT      = 6;

// ===================== device scratch (no cudaMalloc allowed) =====================
__device__ __half g_xh     [(size_t)BATCH * DGPE_IN];      // x as fp16
__device__ __half g_wt_gpi [DGPI_OUT * DGPI_IN];           // [j][k'] masked gpi W^T fp16
__device__ __half g_wm_gpe [DGPE_IN * DGPE_OUT];           // [i][k] masked gpe W (non-transposed)
__device__ float  g_wx32   [DGPE_IN * DGPI_OUT];           // [i][j] masked Wx (fp32, exact)
__device__ float  g_weff32 [DGPE_IN * DGPI_OUT];           // [i][j] W_eff^T fp32
__device__ __half g_weffs  [(size_t)DGPE_IN * 3 * DGPI_OUT]; // [i][ hi | hi | lo ]
__device__ __half g_w1s    [U3 * 2 * DGPI_OUT];            // [n][ hi | lo ]
__device__ __half g_wfull_h[U3 * DGPE_IN];                 // [n][i] fp16 final
__device__ float  g_bias_eff[DGPI_OUT];
__device__ float  g_bias_full[U3];
__device__ __half g_wt_w2  [U3 * U3];
__device__ __half g_h1[(size_t)BATCH * U3];
__device__ __half g_h2[(size_t)BATCH * U3];

// ===================== helpers =====================
__device__ __forceinline__ uint32_t smem_u32(const void* p) {
    return (uint32_t)__cvta_generic_to_shared(p);
}
#define CP_ASYNC16(dst, src) \
    asm volatile("cp.async.cg.shared.global [%0], [%1], 16;\n" :: "r"(dst), "l"(src))
#define CP_ASYNC_COMMIT() asm volatile("cp.async.commit_group;\n" ::: "memory")
#define CP_ASYNC_WAIT(n)  asm volatile("cp.async.wait_group %0;\n" :: "n"(n) : "memory")

__device__ __forceinline__ uint32_t swz64(uint32_t byte_off) {
    return byte_off ^ ((byte_off >> 3) & 0x30);
}

__device__ __forceinline__ void ldmatrix_x4(uint32_t r[4], uint32_t addr) {
    asm volatile("ldmatrix.sync.aligned.m8n8.x4.shared.b16 {%0,%1,%2,%3}, [%4];"
                 : "=r"(r[0]), "=r"(r[1]), "=r"(r[2]), "=r"(r[3]) : "r"(addr));
}

__device__ __forceinline__ void mma_f16(float c[4], const uint32_t a[4],
                                        uint32_t b0, uint32_t b1) {
    asm volatile(
        "mma.sync.aligned.m16n8k16.row.col.f32.f16.f16.f32 "
        "{%0,%1,%2,%3}, {%4,%5,%6,%7}, {%8,%9}, {%0,%1,%2,%3};"
        : "+f"(c[0]), "+f"(c[1]), "+f"(c[2]), "+f"(c[3])
        : "r"(a[0]), "r"(a[1]), "r"(a[2]), "r"(a[3]), "r"(b0), "r"(b1));
}

// ===================== GEMM config =====================
static constexpr int BM = 128, BN = 128, BK = 32, STAGES = 4, NTHREADS = 256;
static constexpr int A_STAGE_BYTES = BM * BK * 2;
static constexpr int B_STAGE_BYTES = BN * BK * 2;
static constexpr int STAGE_BYTES   = A_STAGE_BYTES + B_STAGE_BYTES;
static constexpr int SMEM_BIAS     = 0;
static constexpr int SMEM_TILES    = 1024;
static constexpr int SMEM_TOTAL    = SMEM_TILES + STAGES * STAGE_BYTES; // 66560

// D[m,n] = sum_k A[m,k] * BT[n*ldb + k] (+ bias[n]) (+ Cadd) (optional ReLU)
// out_mode: 0 = fp16 D, 1 = fp32 D.  cadd_mode: 0 none, 1 fp16, 2 fp32.
// A K-split: k < ksplit -> A0 (lda0) else A1 (lda1, k-ksplit). ksplit % BK == 0.
__global__ void __launch_bounds__(NTHREADS, 2)
gemm_f16(const __half* __restrict__ A0, const __half* __restrict__ A1,
         int ksplit, int lda0, int lda1,
         const __half* __restrict__ BT, int ldb, const float* __restrict__ bias,
         const void* __restrict__ Cadd, int ldc, int cadd_mode,
         void* __restrict__ D, int out_mode, int N, int K, int do_relu)
{
    extern __shared__ char smem[];
    float* sb_bias = (float*)(smem + SMEM_BIAS);
    const uint32_t stile = smem_u32(smem) + SMEM_TILES;
    const int tid  = threadIdx.x;
    const int wid  = tid >> 5;
    const int lane = tid & 31;
    const int g    = lane >> 2;
    const int t    = lane & 3;
    const int m0 = blockIdx.y * BM;
    const int n0 = blockIdx.x * BN;
    const int warp_m = (wid >> 2) * 64;
    const int warp_n = (wid & 3) * 32;

    if (tid < BN) sb_bias[tid] = bias ? bias[n0 + tid] : 0.f;

    const int KB = K / BK;

    auto load_stage = [&](int kb) {
        const int s = kb & (STAGES - 1);
        const int k0 = kb * BK;
        const uint32_t a_base = stile + s * STAGE_BYTES;
        const uint32_t b_base = a_base + A_STAGE_BYTES;
        #pragma unroll
        for (int j = 0; j < 2; j++) {
            int idx = tid + j * NTHREADS;
            int row = idx >> 2;
            int c   = idx & 3;
            int kg  = k0 + (c << 3);
            const __half* src = (kg < ksplit)
                ? (A0 + (size_t)(m0 + row) * lda0 + kg)
                : (A1 + (size_t)(m0 + row) * lda1 + (kg - ksplit));
            uint32_t dst = a_base + swz64((uint32_t)(row * 64 + (c << 4)));
            CP_ASYNC16(dst, src);
        }
        #pragma unroll
        for (int j = 0; j < 2; j++) {
            int idx = tid + j * NTHREADS;
            int row = idx >> 2;
            int c   = idx & 3;
            const __half* src = BT + (size_t)(n0 + row) * ldb + k0 + (c << 3);
            uint32_t dst = b_base + swz64((uint32_t)(row * 64 + (c << 4)));
            CP_ASYNC16(dst, src);
        }
        CP_ASYNC_COMMIT();
    };

    float acc[4][4][4];
    #pragma unroll
    for (int mt = 0; mt < 4; mt++)
        #pragma unroll
        for (int nt = 0; nt < 4; nt++)
            #pragma unroll
            for (int r = 0; r < 4; r++) acc[mt][nt][r] = 0.f;

    const int lm_row = (lane & 8) + (lane & 7);
    const int lm_k   = (lane & 16) >> 1;

    load_stage(0); load_stage(1); load_stage(2);

    for (int kb = 0; kb < KB; kb++) {
        if (kb < KB - 3) { CP_ASYNC_WAIT(2); } else { CP_ASYNC_WAIT(0); }
        __syncthreads();
        if (kb + 3 < KB) load_stage(kb + 3);

        const int s = kb & (STAGES - 1);
        const uint32_t As = stile + s * STAGE_BYTES;
        const uint32_t Bs = As + A_STAGE_BYTES;

        #pragma unroll
        for (int ks = 0; ks < 2; ks++) {
            const int kk = ks * 16;
            uint32_t am[4][4], bm[2][4];
            #pragma unroll
            for (int mt = 0; mt < 4; mt++) {
                int row = warp_m + mt * 16 + lm_row;
                ldmatrix_x4(am[mt], As + swz64((uint32_t)(row * 64 + (kk + lm_k) * 2)));
            }
            #pragma unroll
            for (int pr = 0; pr < 2; pr++) {
                int row = warp_n + pr * 16 + lm_row;
                ldmatrix_x4(bm[pr], Bs + swz64((uint32_t)(row * 64 + (kk + lm_k) * 2)));
            }
            #pragma unroll
            for (int mt = 0; mt < 4; mt++)
                #pragma unroll
                for (int nt = 0; nt < 4; nt++)
                    mma_f16(acc[mt][nt], am[mt], bm[nt >> 1][nt & 1], bm[nt >> 1][(nt & 1) + 2]);
        }
    }

    // epilogue
    #pragma unroll
    for (int mt = 0; mt < 4; mt++) {
        const int row = m0 + warp_m + mt * 16 + g;
        #pragma unroll
        for (int nt = 0; nt < 4; nt++) {
            const int cb = warp_n + nt * 8 + t * 2;
            const int col = n0 + cb;
            float b0 = sb_bias[cb], b1 = sb_bias[cb + 1];
            float2 v0 = make_float2(acc[mt][nt][0] + b0, acc[mt][nt][1] + b1);
            float2 v1 = make_float2(acc[mt][nt][2] + b0, acc[mt][nt][3] + b1);
            if (cadd_mode == 1) {
                const __half* C = (const __half*)Cadd;
                __half2 c0 = *reinterpret_cast<const __half2*>(C + (size_t)row * ldc + col);
                __half2 c1 = *reinterpret_cast<const __half2*>(C + (size_t)(row + 8) * ldc + col);
                v0.x += __half2float(c0.x); v0.y += __half2float(c0.y);
                v1.x += __half2float(c1.x); v1.y += __half2float(c1.y);
            } else if (cadd_mode == 2) {
                const float* C = (const float*)Cadd;
                float2 c0 = *reinterpret_cast<const float2*>(C + (size_t)row * ldc + col);
                float2 c1 = *reinterpret_cast<const float2*>(C + (size_t)(row + 8) * ldc + col);
                v0.x += c0.x; v0.y += c0.y;
                v1.x += c1.x; v1.y += c1.y;
            }
            if (do_relu) {
                v0.x = fmaxf(v0.x, 0.f); v0.y = fmaxf(v0.y, 0.f);
                v1.x = fmaxf(v1.x, 0.f); v1.y = fmaxf(v1.y, 0.f);
            }
            if (out_mode == 0) {
                __half* Dh = (__half*)D;
                *reinterpret_cast<__half2*>(Dh + (size_t)row * N + col)       = __floats2half2_rn(v0.x, v0.y);
                *reinterpret_cast<__half2*>(Dh + (size_t)(row + 8) * N + col) = __floats2half2_rn(v1.x, v1.y);
            } else {
                float* Df = (float*)D;
                *reinterpret_cast<float2*>(Df + (size_t)row * N + col)       = v0;
                *reinterpret_cast<float2*>(Df + (size_t)(row + 8) * N + col) = v1;
            }
        }
    }
}

// ===================== weight prep kernels =====================
__global__ void transpose_mask(const float* __restrict__ w, const float* __restrict__ mask,
                               __half* __restrict__ wt, int K, int N)
{
    __shared__ float tile[32][33];
    const int k0 = blockIdx.x * 32, n0 = blockIdx.y * 32;
    const int tx = threadIdx.x, ty = threadIdx.y;
    #pragma unroll
    for (int j = 0; j < 32; j += 8)
        tile[ty + j][tx] = w[(size_t)(k0 + ty + j) * N + n0 + tx];
    __syncthreads();
    #pragma unroll
    for (int j = 0; j < 32; j += 8) {
        const int n = n0 + ty + j, k = k0 + tx;
        float v = tile[tx][ty + j];
        if (mask) v *= mask[(size_t)n * K + k];
        wt[(size_t)n * K + k] = __float2half_rn(v);
    }
}

// W1^T hi/lo split: w1s[n][k] = hi(W1[k,n]), w1s[n][K+k] = lo. lda = 2K.
__global__ void transpose_split_w1(const float* __restrict__ w, __half* __restrict__ w1s,
                                   int K, int N)
{
    __shared__ float tile[32][33];
    const int k0 = blockIdx.x * 32, n0 = blockIdx.y * 32;
    const int tx = threadIdx.x, ty = threadIdx.y;
    #pragma unroll
    for (int j = 0; j < 32; j += 8)
        tile[ty + j][tx] = w[(size_t)(k0 + ty + j) * N + n0 + tx];
    __syncthreads();
    #pragma unroll
    for (int j = 0; j < 32; j += 8) {
        const int n = n0 + ty + j, k = k0 + tx;
        float v = tile[tx][ty + j];
        __half hi = __float2half_rn(v);
        __half lo = __float2half_rn(v - __half2float(hi));
        w1s[(size_t)n * (2 * K) + k]     = hi;
        w1s[(size_t)n * (2 * K) + K + k] = lo;
    }
}

__global__ void mask_apply_nt(const float* __restrict__ w, const float* __restrict__ mask,
                              int mstride, __half* __restrict__ out, int J)
{
    __shared__ float mt[32][33];
    const int i0 = blockIdx.y * 32, j0 = blockIdx.x * 32;
    const int tx = threadIdx.x, ty = threadIdx.y;
    #pragma unroll
    for (int jj = 0; jj < 32; jj += 8)
        mt[ty + jj][tx] = mask[(size_t)(j0 + ty + jj) * mstride + i0 + tx];
    __syncthreads();
    #pragma unroll
    for (int jj = 0; jj < 32; jj += 8) {
        const int i = i0 + ty + jj, j = j0 + tx;
        out[(size_t)i * J + j] = __float2half_rn(w[(size_t)i * J + j] * mt[tx][ty + jj]);
    }
}

__global__ void mask_apply_nt_f32(const float* __restrict__ w, const float* __restrict__ mask,
                                  int mstride, float* __restrict__ out, int J)
{
    __shared__ float mt[32][33];
    const int i0 = blockIdx.y * 32, j0 = blockIdx.x * 32;
    const int tx = threadIdx.x, ty = threadIdx.y;
    #pragma unroll
    for (int jj = 0; jj < 32; jj += 8)
        mt[ty + jj][tx] = mask[(size_t)(j0 + ty + jj) * mstride + i0 + tx];
    __syncthreads();
    #pragma unroll
    for (int jj = 0; jj < 32; jj += 8) {
        const int i = i0 + ty + jj, j = j0 + tx;
        out[(size_t)i * J + j] = w[(size_t)i * J + j] * mt[tx][ty + jj];
    }
}

// weffs[i][ j ]=hi, [J+j]=hi, [2J+j]=lo  (3-segment layout for single-pass hi/lo GEMM)
__global__ void split_hilo3(const float* __restrict__ src, __half* __restrict__ dst, int J)
{
    const int i = blockIdx.y;
    const int j = blockIdx.x * blockDim.x + threadIdx.x;
    float v = src[(size_t)i * J + j];
    __half hi = __float2half_rn(v);
    __half lo = __float2half_rn(v - __half2float(hi));
    const size_t base = (size_t)i * (3 * J);
    dst[base + j]         = hi;
    dst[base + J + j]     = hi;
    dst[base + 2 * J + j] = lo;
}

// bias_eff[n] = gpi_b[n] + sum_j gpe_b[j] * gpi_w[1536+j][n] * gpi_mask[n][1536+j]
// (reads fp32 inputs directly — no dependency on the gpi transpose)
__global__ void bias_eff_kernel(const float* __restrict__ gpi_w, const float* __restrict__ gpi_mask,
                                const float* __restrict__ gpe_b,
                                const float* __restrict__ gpi_b, float* __restrict__ be)
{
    const int n = blockIdx.x * 8 + (threadIdx.x >> 5);
    const int lane = threadIdx.x & 31;
    const float* mrow = gpi_mask + (size_t)n * DGPI_IN + DGPE_IN;
    float s0 = 0.f, s1 = 0.f;
    for (int j = lane; j < DGPE_OUT; j += 64) {
        s0 += gpi_w[(size_t)(DGPE_IN + j) * DGPI_OUT + n] * mrow[j] * gpe_b[j];
        int j2 = j + 32;
        s1 += gpi_w[(size_t)(DGPE_IN + j2) * DGPI_OUT + n] * mrow[j2] * gpe_b[j2];
    }
    float s = s0 + s1;
    #pragma unroll
    for (int off = 16; off; off >>= 1) s += __shfl_xor_sync(0xffffffffu, s, off);
    if (lane == 0) be[n] = gpi_b[n] + s;
}

// bias_full[n] = b1[n] + sum_j bias_eff[j] * w1[j*U3 + n]  — warp per n, unrolled
__global__ void bias_full_kernel(const float* __restrict__ be, const float* __restrict__ w1,
                                 const float* __restrict__ b1, float* __restrict__ bf)
{
    const int n = blockIdx.x * 8 + (threadIdx.x >> 5);
    const int lane = threadIdx.x & 31;
    float s0 = 0.f, s1 = 0.f;
    for (int j = lane; j < DGPI_OUT; j += 64) {
        s0 += be[j] * w1[(size_t)j * U3 + n];
        s1 += be[j + 32] * w1[(size_t)(j + 32) * U3 + n];
    }
    float s = s0 + s1;
    #pragma unroll
    for (int off = 16; off; off >>= 1) s += __shfl_xor_sync(0xffffffffu, s, off);
    if (lane == 0) bf[n] = b1[n] + s;
}

__global__ void convert_f2h(const float* __restrict__ src, __half* __restrict__ dst, int n)
{
    int i = (blockIdx.x * blockDim.x + threadIdx.x) * 4;
    if (i < n) {
        float4 v = *reinterpret_cast<const float4*>(src + i);
        *reinterpret_cast<__half2*>(dst + i)     = __floats2half2_rn(v.x, v.y);
        *reinterpret_cast<__half2*>(dst + i + 2) = __floats2half2_rn(v.z, v.w);
    }
}

__global__ void final_layer(const __half* __restrict__ h, const float* __restrict__ w3,
                            const float* __restrict__ b3, float* __restrict__ out)
{
    __shared__ float sw[U3 * ACT];
    __shared__ float sbb[ACT];
    const int tid = threadIdx.x;
    for (int i = tid; i < U3 * ACT; i += blockDim.x) sw[i] = w3[i];
    if (tid < ACT) sbb[tid] = b3[tid];
    __syncthreads();
    const int wid = tid >> 5, lane = tid & 31;
    const int row = blockIdx.x * (blockDim.x >> 5) + wid;
    const __half* hr = h + (size_t)row * U3;
    float acc[ACT] = {0.f, 0.f, 0.f, 0.f, 0.f, 0.f};
    for (int k0 = lane * 2; k0 < U3; k0 += 64) {
        __half2 hv = *reinterpret_cast<const __half2*>(hr + k0);
        float x0 = __half2float(hv.x), x1 = __half2float(hv.y);
        #pragma unroll
        for (int n = 0; n < ACT; n++)
            acc[n] += x0 * sw[k0 * ACT + n] + x1 * sw[(k0 + 1) * ACT + n];
    }
    #pragma unroll
    for (int n = 0; n < ACT; n++)
        #pragma unroll
        for (int off = 16; off; off >>= 1)
            acc[n] += __shfl_xor_sync(0xffffffffu, acc[n], off);
    if (lane < ACT) out[(size_t)row * ACT + lane] = fmaxf(acc[lane] + sbb[lane], 0.f);
}

// ===================== launch =====================
extern "C" void kernel_launch(void* const* d_in, const int* in_sizes, int n_in,
                              void* d_out, int out_size)
{
    const float* x        = (const float*)d_in[0];
    const float* gpe_mask = (const float*)d_in[1];
    const float* gpe_w    = (const float*)d_in[2];
    const float* gpe_b    = (const float*)d_in[3];
    const float* gpi_mask = (const float*)d_in[4];
    const float* gpi_w    = (const float*)d_in[5];
    const float* gpi_b    = (const float*)d_in[6];
    const float* w1       = (const float*)d_in[7];
    const float* b1       = (const float*)d_in[8];
    const float* w2       = (const float*)d_in[9];
    const float* b2       = (const float*)d_in[10];
    const float* w3       = (const float*)d_in[11];
    const float* b3       = (const float*)d_in[12];
    float* out = (float*)d_out;

    __half *xh, *wt_gpi, *wm_gpe, *weffs, *w1s, *wfull_h, *wt_w2, *h1, *h2;
    float *wx32, *weff32, *bias_eff, *bias_full;
    cudaGetSymbolAddress((void**)&xh,        g_xh);
    cudaGetSymbolAddress((void**)&wt_gpi,    g_wt_gpi);
    cudaGetSymbolAddress((void**)&wm_gpe,    g_wm_gpe);
    cudaGetSymbolAddress((void**)&wx32,      g_wx32);
    cudaGetSymbolAddress((void**)&weff32,    g_weff32);
    cudaGetSymbolAddress((void**)&weffs,     g_weffs);
    cudaGetSymbolAddress((void**)&w1s,       g_w1s);
    cudaGetSymbolAddress((void**)&wfull_h,   g_wfull_h);
    cudaGetSymbolAddress((void**)&bias_eff,  g_bias_eff);
    cudaGetSymbolAddress((void**)&bias_full, g_bias_full);
    cudaGetSymbolAddress((void**)&wt_w2,     g_wt_w2);
    cudaGetSymbolAddress((void**)&h1,        g_h1);
    cudaGetSymbolAddress((void**)&h2,        g_h2);

    cudaFuncSetAttribute(gemm_f16, cudaFuncAttributeMaxDynamicSharedMemorySize, SMEM_TOTAL);

    static cudaStream_t sA = nullptr, sB = nullptr, sC = nullptr;
    static cudaEvent_t evRoot, evGpi, evWx, evW1s, evW2, evWfull, evBias;
    if (sA == nullptr) {
        cudaStreamCreateWithFlags(&sA, cudaStreamNonBlocking);
        cudaStreamCreateWithFlags(&sB, cudaStreamNonBlocking);
        cudaStreamCreateWithFlags(&sC, cudaStreamNonBlocking);
        cudaEventCreateWithFlags(&evRoot,  cudaEventDisableTiming);
        cudaEventCreateWithFlags(&evGpi,   cudaEventDisableTiming);
        cudaEventCreateWithFlags(&evWx,    cudaEventDisableTiming);
        cudaEventCreateWithFlags(&evW1s,   cudaEventDisableTiming);
        cudaEventCreateWithFlags(&evW2,    cudaEventDisableTiming);
        cudaEventCreateWithFlags(&evWfull, cudaEventDisableTiming);
        cudaEventCreateWithFlags(&evBias,  cudaEventDisableTiming);
    }

    const dim3 tb(32, 8);
    const int nx = BATCH * DGPE_IN;

    // ---- fork ----
    cudaEventRecord(evRoot, 0);
    cudaStreamWaitEvent(sA, evRoot, 0);
    cudaStreamWaitEvent(sB, evRoot, 0);
    cudaStreamWaitEvent(sC, evRoot, 0);

    // L (legacy stream): the big independent x conversion, overlapped with all prep
    convert_f2h<<<(nx / 4 + 255) / 256, 256>>>(x, xh, nx);

    // sA: fully parallel bias chain (no transpose dependency) + gpi transpose
    bias_eff_kernel<<<DGPI_OUT / 8, 256, 0, sA>>>(gpi_w, gpi_mask, gpe_b, gpi_b, bias_eff);
    bias_full_kernel<<<U3 / 8, 256, 0, sA>>>(bias_eff, w1, b1, bias_full);
    cudaEventRecord(evBias, sA);
    transpose_mask<<<dim3(DGPI_IN / 32, DGPI_OUT / 32), tb, 0, sA>>>(gpi_w, gpi_mask, wt_gpi, DGPI_IN, DGPI_OUT);
    cudaEventRecord(evGpi, sA);

    // sC: wx32 (needed by W_eff), then w1 split and w2 transpose
    mask_apply_nt_f32<<<dim3(DGPI_OUT / 32, DGPE_IN / 32), tb, 0, sC>>>(gpi_w, gpi_mask, DGPI_IN, wx32, DGPI_OUT);
    cudaEventRecord(evWx, sC);
    transpose_split_w1<<<dim3(DGPI_OUT / 32, U3 / 32), tb, 0, sC>>>(w1, w1s, DGPI_OUT, U3);
    cudaEventRecord(evW1s, sC);
    transpose_mask<<<dim3(U3 / 32, U3 / 32), tb, 0, sC>>>(w2, nullptr, wt_w2, U3, U3);
    cudaEventRecord(evW2, sC);

    // sB: gpe mask -> W_eff GEMM -> split -> single-pass W_full GEMM
    mask_apply_nt<<<dim3(DGPE_OUT / 32, DGPE_IN / 32), tb, 0, sB>>>(gpe_w, gpe_mask, DGPE_IN, wm_gpe, DGPE_OUT);
    cudaStreamWaitEvent(sB, evGpi, 0);
    cudaStreamWaitEvent(sB, evWx, 0);
    // W_eff^T fp32 [i][j] = Wgpe@Wg + Wx^T   (7.2 GF)
    gemm_f16<<<dim3(DGPI_OUT / BN, DGPE_IN / BM), NTHREADS, SMEM_TOTAL, sB>>>(
        wm_gpe, wm_gpe, DGPE_OUT, DGPE_OUT, DGPE_OUT,
        wt_gpi + DGPE_IN, DGPI_IN, nullptr,
        wx32, DGPI_OUT, 2, weff32, 1, DGPI_OUT, DGPE_OUT, 0);
    split_hilo3<<<dim3(DGPI_OUT / 256, DGPE_IN), 256, 0, sB>>>(weff32, weffs, DGPI_OUT);
    cudaStreamWaitEvent(sB, evW1s, 0);
    // W_full[n][i] single pass over K=4608: hi@hi | lo@hi | hi@lo   (7.2 GF)
    gemm_f16<<<dim3(DGPE_IN / BN, U3 / BM), NTHREADS, SMEM_TOTAL, sB>>>(
        w1s, w1s, 2 * DGPI_OUT, 2 * DGPI_OUT, 2 * DGPI_OUT,
        weffs, 3 * DGPI_OUT, nullptr,
        nullptr, 0, 0, wfull_h, 0, DGPE_IN, 3 * DGPI_OUT, 0);
    cudaEventRecord(evWfull, sB);

    // ---- join ----
    cudaStreamWaitEvent(0, evWfull, 0);
    cudaStreamWaitEvent(0, evBias, 0);
    cudaStreamWaitEvent(0, evW2, 0);

    // h1 = relu(x @ W_full + bias_full)   (25.8 GF)
    gemm_f16<<<dim3(U3 / BN, BATCH / BM), NTHREADS, SMEM_TOTAL>>>(
        xh, xh, DGPE_IN, DGPE_IN, DGPE_IN,
        wfull_h, DGPE_IN, bias_full,
        nullptr, 0, 0, h1, 0, U3, DGPE_IN, 1);
    // h2 = relu(h1 @ w2 + b2)   (8.6 GF)
    gemm_f16<<<dim3(U3 / BN, BATCH / BM), NTHREADS, SMEM_TOTAL>>>(
        h1, h1, U3, U3, U3,
        wt_w2, U3, b2,
        nullptr, 0, 0, h2, 0, U3, U3, 1);
    // out = relu(h2 @ w3 + b3)
    final_layer<<<BATCH / 8, 256>>>(h2, w3, b3, out);
}

// round 10
// speedup vs baseline: 1.1648x; 1.1648x over previous
#include <cuda_runtime.h>
#include <cuda_fp16.h>
#include <cstdint>

// ===================== problem dims =====================
static constexpr int BATCH    = 16384;
static constexpr int DGPE_IN  = 1536;
static constexpr int DGPE_OUT = 1536;
static constexpr int DGPI_IN  = 3072;
static constexpr int DGPI_OUT = 1536;
static constexpr int U3       = 512;
static constexpr int ACT      = 6;

// ===================== device scratch (no cudaMalloc allowed) =====================
__device__ __half g_xh     [(size_t)BATCH * DGPE_IN];        // x as fp16
__device__ __half g_wt_gpi [DGPI_OUT * DGPI_IN];             // [j][k'] masked gpi W^T fp16
__device__ __half g_wm_gpe [DGPE_IN * DGPE_OUT];             // [i][k] masked gpe W (non-transposed)
__device__ float  g_wx32   [DGPE_IN * DGPI_OUT];             // [i][j] masked Wx (fp32, exact)
__device__ __half g_weffs  [(size_t)DGPE_IN * 3 * DGPI_OUT]; // [i][ hi | hi | lo ]
__device__ __half g_w1s    [U3 * 2 * DGPI_OUT];              // [n][ hi | lo ]
__device__ float  g_wf_p0  [U3 * DGPE_IN];                   // W_full partials (fp32)
__device__ float  g_wf_p1  [U3 * DGPE_IN];
__device__ float  g_wf_p2  [U3 * DGPE_IN];
__device__ __half g_wfull_h[U3 * DGPE_IN];                   // [n][i] fp16 final
__device__ float  g_bias_eff[DGPI_OUT];
__device__ float  g_bias_full[U3];
__device__ __half g_wt_w2  [U3 * U3];
__device__ __half g_h1[(size_t)BATCH * U3];
__device__ __half g_h2[(size_t)BATCH * U3];

// ===================== helpers =====================
__device__ __forceinline__ uint32_t smem_u32(const void* p) {
    return (uint32_t)__cvta_generic_to_shared(p);
}
#define CP_ASYNC16(dst, src) \
    asm volatile("cp.async.cg.shared.global [%0], [%1], 16;\n" :: "r"(dst), "l"(src))
#define CP_ASYNC_COMMIT() asm volatile("cp.async.commit_group;\n" ::: "memory")
#define CP_ASYNC_WAIT(n)  asm volatile("cp.async.wait_group %0;\n" :: "n"(n) : "memory")

__device__ __forceinline__ uint32_t swz64(uint32_t byte_off) {
    return byte_off ^ ((byte_off >> 3) & 0x30);
}

__device__ __forceinline__ void ldmatrix_x4(uint32_t r[4], uint32_t addr) {
    asm volatile("ldmatrix.sync.aligned.m8n8.x4.shared.b16 {%0,%1,%2,%3}, [%4];"
                 : "=r"(r[0]), "=r"(r[1]), "=r"(r[2]), "=r"(r[3]) : "r"(addr));
}

__device__ __forceinline__ void mma_f16(float c[4], const uint32_t a[4],
                                        uint32_t b0, uint32_t b1) {
    asm volatile(
        "mma.sync.aligned.m16n8k16.row.col.f32.f16.f16.f32 "
        "{%0,%1,%2,%3}, {%4,%5,%6,%7}, {%8,%9}, {%0,%1,%2,%3};"
        : "+f"(c[0]), "+f"(c[1]), "+f"(c[2]), "+f"(c[3])
        : "r"(a[0]), "r"(a[1]), "r"(a[2]), "r"(a[3]), "r"(b0), "r"(b1));
}

// ===================== GEMM config =====================
static constexpr int BM = 128, BN = 128, BK = 32, STAGES = 4, NTHREADS = 256;
static constexpr int A_STAGE_BYTES = BM * BK * 2;
static constexpr int B_STAGE_BYTES = BN * BK * 2;
static constexpr int STAGE_BYTES   = A_STAGE_BYTES + B_STAGE_BYTES;
static constexpr int SMEM_BIAS     = 0;
static constexpr int SMEM_TILES    = 1024;
static constexpr int SMEM_TOTAL    = SMEM_TILES + STAGES * STAGE_BYTES; // 66560

// D[m,n] = sum_k A[m,k] * BT[n*ldb + k] (+ bias[n]) (+ Cadd) (optional ReLU)
// out_mode: 0 = fp16 D (ld N), 1 = fp32 D (ld N),
//           2 = fp16 3-seg hi|hi|lo (ld 3N): hi at col, hi at N+col, lo at 2N+col.
// cadd_mode: 0 none, 1 fp16, 2 fp32.
// A K-split: k < ksplit -> A0 (lda0) else A1 (lda1, k-ksplit). ksplit % BK == 0.
__global__ void __launch_bounds__(NTHREADS, 2)
gemm_f16(const __half* __restrict__ A0, const __half* __restrict__ A1,
         int ksplit, int lda0, int lda1,
         const __half* __restrict__ BT, int ldb, const float* __restrict__ bias,
         const void* __restrict__ Cadd, int ldc, int cadd_mode,
         void* __restrict__ D, int out_mode, int N, int K, int do_relu)
{
    extern __shared__ char smem[];
    float* sb_bias = (float*)(smem + SMEM_BIAS);
    const uint32_t stile = smem_u32(smem) + SMEM_TILES;
    const int tid  = threadIdx.x;
    const int wid  = tid >> 5;
    const int lane = tid & 31;
    const int g    = lane >> 2;
    const int t    = lane & 3;
    const int m0 = blockIdx.y * BM;
    const int n0 = blockIdx.x * BN;
    const int warp_m = (wid >> 2) * 64;
    const int warp_n = (wid & 3) * 32;

    if (tid < BN) sb_bias[tid] = bias ? bias[n0 + tid] : 0.f;

    const int KB = K / BK;

    auto load_stage = [&](int kb) {
        const int s = kb & (STAGES - 1);
        const int k0 = kb * BK;
        const uint32_t a_base = stile + s * STAGE_BYTES;
        const uint32_t b_base = a_base + A_STAGE_BYTES;
        #pragma unroll
        for (int j = 0; j < 2; j++) {
            int idx = tid + j * NTHREADS;
            int row = idx >> 2;
            int c   = idx & 3;
            int kg  = k0 + (c << 3);
            const __half* src = (kg < ksplit)
                ? (A0 + (size_t)(m0 + row) * lda0 + kg)
                : (A1 + (size_t)(m0 + row) * lda1 + (kg - ksplit));
            uint32_t dst = a_base + swz64((uint32_t)(row * 64 + (c << 4)));
            CP_ASYNC16(dst, src);
        }
        #pragma unroll
        for (int j = 0; j < 2; j++) {
            int idx = tid + j * NTHREADS;
            int row = idx >> 2;
            int c   = idx & 3;
            const __half* src = BT + (size_t)(n0 + row) * ldb + k0 + (c << 3);
            uint32_t dst = b_base + swz64((uint32_t)(row * 64 + (c << 4)));
            CP_ASYNC16(dst, src);
        }
        CP_ASYNC_COMMIT();
    };

    float acc[4][4][4];
    #pragma unroll
    for (int mt = 0; mt < 4; mt++)
        #pragma unroll
        for (int nt = 0; nt < 4; nt++)
            #pragma unroll
            for (int r = 0; r < 4; r++) acc[mt][nt][r] = 0.f;

    const int lm_row = (lane & 8) + (lane & 7);
    const int lm_k   = (lane & 16) >> 1;

    load_stage(0); load_stage(1); load_stage(2);

    for (int kb = 0; kb < KB; kb++) {
        if (kb < KB - 3) { CP_ASYNC_WAIT(2); } else { CP_ASYNC_WAIT(0); }
        __syncthreads();
        if (kb + 3 < KB) load_stage(kb + 3);

        const int s = kb & (STAGES - 1);
        const uint32_t As = stile + s * STAGE_BYTES;
        const uint32_t Bs = As + A_STAGE_BYTES;

        #pragma unroll
        for (int ks = 0; ks < 2; ks++) {
            const int kk = ks * 16;
            uint32_t am[4][4], bm[2][4];
            #pragma unroll
            for (int mt = 0; mt < 4; mt++) {
                int row = warp_m + mt * 16 + lm_row;
                ldmatrix_x4(am[mt], As + swz64((uint32_t)(row * 64 + (kk + lm_k) * 2)));
            }
            #pragma unroll
            for (int pr = 0; pr < 2; pr++) {
                int row = warp_n + pr * 16 + lm_row;
                ldmatrix_x4(bm[pr], Bs + swz64((uint32_t)(row * 64 + (kk + lm_k) * 2)));
            }
            #pragma unroll
            for (int mt = 0; mt < 4; mt++)
                #pragma unroll
                for (int nt = 0; nt < 4; nt++)
                    mma_f16(acc[mt][nt], am[mt], bm[nt >> 1][nt & 1], bm[nt >> 1][(nt & 1) + 2]);
        }
    }

    // epilogue
    #pragma unroll
    for (int mt = 0; mt < 4; mt++) {
        const int row = m0 + warp_m + mt * 16 + g;
        #pragma unroll
        for (int nt = 0; nt < 4; nt++) {
            const int cb = warp_n + nt * 8 + t * 2;
            const int col = n0 + cb;
            float b0 = sb_bias[cb], b1 = sb_bias[cb + 1];
            float2 v0 = make_float2(acc[mt][nt][0] + b0, acc[mt][nt][1] + b1);
            float2 v1 = make_float2(acc[mt][nt][2] + b0, acc[mt][nt][3] + b1);
            if (cadd_mode == 1) {
                const __half* C = (const __half*)Cadd;
                __half2 c0 = *reinterpret_cast<const __half2*>(C + (size_t)row * ldc + col);
                __half2 c1 = *reinterpret_cast<const __half2*>(C + (size_t)(row + 8) * ldc + col);
                v0.x += __half2float(c0.x); v0.y += __half2float(c0.y);
                v1.x += __half2float(c1.x); v1.y += __half2float(c1.y);
            } else if (cadd_mode == 2) {
                const float* C = (const float*)Cadd;
                float2 c0 = *reinterpret_cast<const float2*>(C + (size_t)row * ldc + col);
                float2 c1 = *reinterpret_cast<const float2*>(C + (size_t)(row + 8) * ldc + col);
                v0.x += c0.x; v0.y += c0.y;
                v1.x += c1.x; v1.y += c1.y;
            }
            if (do_relu) {
                v0.x = fmaxf(v0.x, 0.f); v0.y = fmaxf(v0.y, 0.f);
                v1.x = fmaxf(v1.x, 0.f); v1.y = fmaxf(v1.y, 0.f);
            }
            if (out_mode == 0) {
                __half* Dh = (__half*)D;
                *reinterpret_cast<__half2*>(Dh + (size_t)row * N + col)       = __floats2half2_rn(v0.x, v0.y);
                *reinterpret_cast<__half2*>(Dh + (size_t)(row + 8) * N + col) = __floats2half2_rn(v1.x, v1.y);
            } else if (out_mode == 1) {
                float* Df = (float*)D;
                *reinterpret_cast<float2*>(Df + (size_t)row * N + col)       = v0;
                *reinterpret_cast<float2*>(Df + (size_t)(row + 8) * N + col) = v1;
            } else {
                // 3-seg hi|hi|lo, ld = 3N
                __half* Dh = (__half*)D;
                __half2 h0 = __floats2half2_rn(v0.x, v0.y);
                __half2 h1v = __floats2half2_rn(v1.x, v1.y);
                __half2 l0 = __floats2half2_rn(v0.x - __half2float(h0.x),
                                               v0.y - __half2float(h0.y));
                __half2 l1 = __floats2half2_rn(v1.x - __half2float(h1v.x),
                                               v1.y - __half2float(h1v.y));
                size_t base0 = (size_t)row * (3 * N);
                size_t base1 = (size_t)(row + 8) * (3 * N);
                *reinterpret_cast<__half2*>(Dh + base0 + col)         = h0;
                *reinterpret_cast<__half2*>(Dh + base0 + N + col)     = h0;
                *reinterpret_cast<__half2*>(Dh + base0 + 2 * N + col) = l0;
                *reinterpret_cast<__half2*>(Dh + base1 + col)         = h1v;
                *reinterpret_cast<__half2*>(Dh + base1 + N + col)     = h1v;
                *reinterpret_cast<__half2*>(Dh + base1 + 2 * N + col) = l1;
            }
        }
    }
}

// ===================== weight prep kernels =====================
__global__ void transpose_mask(const float* __restrict__ w, const float* __restrict__ mask,
                               __half* __restrict__ wt, int K, int N)
{
    __shared__ float tile[32][33];
    const int k0 = blockIdx.x * 32, n0 = blockIdx.y * 32;
    const int tx = threadIdx.x, ty = threadIdx.y;
    #pragma unroll
    for (int j = 0; j < 32; j += 8)
        tile[ty + j][tx] = w[(size_t)(k0 + ty + j) * N + n0 + tx];
    __syncthreads();
    #pragma unroll
    for (int j = 0; j < 32; j += 8) {
        const int n = n0 + ty + j, k = k0 + tx;
        float v = tile[tx][ty + j];
        if (mask) v *= mask[(size_t)n * K + k];
        wt[(size_t)n * K + k] = __float2half_rn(v);
    }
}

// W1^T hi/lo split: w1s[n][k] = hi(W1[k,n]), w1s[n][K+k] = lo. lda = 2K.
__global__ void transpose_split_w1(const float* __restrict__ w, __half* __restrict__ w1s,
                                   int K, int N)
{
    __shared__ float tile[32][33];
    const int k0 = blockIdx.x * 32, n0 = blockIdx.y * 32;
    const int tx = threadIdx.x, ty = threadIdx.y;
    #pragma unroll
    for (int j = 0; j < 32; j += 8)
        tile[ty + j][tx] = w[(size_t)(k0 + ty + j) * N + n0 + tx];
    __syncthreads();
    #pragma unroll
    for (int j = 0; j < 32; j += 8) {
        const int n = n0 + ty + j, k = k0 + tx;
        float v = tile[tx][ty + j];
        __half hi = __float2half_rn(v);
        __half lo = __float2half_rn(v - __half2float(hi));
        w1s[(size_t)n * (2 * K) + k]     = hi;
        w1s[(size_t)n * (2 * K) + K + k] = lo;
    }
}

__global__ void mask_apply_nt(const float* __restrict__ w, const float* __restrict__ mask,
                              int mstride, __half* __restrict__ out, int J)
{
    __shared__ float mt[32][33];
    const int i0 = blockIdx.y * 32, j0 = blockIdx.x * 32;
    const int tx = threadIdx.x, ty = threadIdx.y;
    #pragma unroll
    for (int jj = 0; jj < 32; jj += 8)
        mt[ty + jj][tx] = mask[(size_t)(j0 + ty + jj) * mstride + i0 + tx];
    __syncthreads();
    #pragma unroll
    for (int jj = 0; jj < 32; jj += 8) {
        const int i = i0 + ty + jj, j = j0 + tx;
        out[(size_t)i * J + j] = __float2half_rn(w[(size_t)i * J + j] * mt[tx][ty + jj]);
    }
}

__global__ void mask_apply_nt_f32(const float* __restrict__ w, const float* __restrict__ mask,
                                  int mstride, float* __restrict__ out, int J)
{
    __shared__ float mt[32][33];
    const int i0 = blockIdx.y * 32, j0 = blockIdx.x * 32;
    const int tx = threadIdx.x, ty = threadIdx.y;
    #pragma unroll
    for (int jj = 0; jj < 32; jj += 8)
        mt[ty + jj][tx] = mask[(size_t)(j0 + ty + jj) * mstride + i0 + tx];
    __syncthreads();
    #pragma unroll
    for (int jj = 0; jj < 32; jj += 8) {
        const int i = i0 + ty + jj, j = j0 + tx;
        out[(size_t)i * J + j] = w[(size_t)i * J + j] * mt[tx][ty + jj];
    }
}

// wfull_h = f16(p0 + p1 + p2), vectorized
__global__ void reduce3_f16(const float* __restrict__ p0, const float* __restrict__ p1,
                            const float* __restrict__ p2, __half* __restrict__ out)
{
    int i = (blockIdx.x * blockDim.x + threadIdx.x) * 4;
    float4 a = *reinterpret_cast<const float4*>(p0 + i);
    float4 b = *reinterpret_cast<const float4*>(p1 + i);
    float4 c = *reinterpret_cast<const float4*>(p2 + i);
    *reinterpret_cast<__half2*>(out + i)     = __floats2half2_rn(a.x + b.x + c.x, a.y + b.y + c.y);
    *reinterpret_cast<__half2*>(out + i + 2) = __floats2half2_rn(a.z + b.z + c.z, a.w + b.w + c.w);
}

// bias_eff[n] = gpi_b[n] + sum_j gpe_b[j] * gpi_w[1536+j][n] * gpi_mask[n][1536+j]
__global__ void bias_eff_kernel(const float* __restrict__ gpi_w, const float* __restrict__ gpi_mask,
                                const float* __restrict__ gpe_b,
                                const float* __restrict__ gpi_b, float* __restrict__ be)
{
    const int n = blockIdx.x * 8 + (threadIdx.x >> 5);
    const int lane = threadIdx.x & 31;
    const float* mrow = gpi_mask + (size_t)n * DGPI_IN + DGPE_IN;
    float s0 = 0.f, s1 = 0.f;
    for (int j = lane; j < DGPE_OUT; j += 64) {
        s0 += gpi_w[(size_t)(DGPE_IN + j) * DGPI_OUT + n] * mrow[j] * gpe_b[j];
        int j2 = j + 32;
        s1 += gpi_w[(size_t)(DGPE_IN + j2) * DGPI_OUT + n] * mrow[j2] * gpe_b[j2];
    }
    float s = s0 + s1;
    #pragma unroll
    for (int off = 16; off; off >>= 1) s += __shfl_xor_sync(0xffffffffu, s, off);
    if (lane == 0) be[n] = gpi_b[n] + s;
}

__global__ void bias_full_kernel(const float* __restrict__ be, const float* __restrict__ w1,
                                 const float* __restrict__ b1, float* __restrict__ bf)
{
    const int n = blockIdx.x * 8 + (threadIdx.x >> 5);
    const int lane = threadIdx.x & 31;
    float s0 = 0.f, s1 = 0.f;
    for (int j = lane; j < DGPI_OUT; j += 64) {
        s0 += be[j] * w1[(size_t)j * U3 + n];
        s1 += be[j + 32] * w1[(size_t)(j + 32) * U3 + n];
    }
    float s = s0 + s1;
    #pragma unroll
    for (int off = 16; off; off >>= 1) s += __shfl_xor_sync(0xffffffffu, s, off);
    if (lane == 0) bf[n] = b1[n] + s;
}

__global__ void convert_f2h(const float* __restrict__ src, __half* __restrict__ dst, int n)
{
    int i = (blockIdx.x * blockDim.x + threadIdx.x) * 4;
    if (i < n) {
        float4 v = *reinterpret_cast<const float4*>(src + i);
        *reinterpret_cast<__half2*>(dst + i)     = __floats2half2_rn(v.x, v.y);
        *reinterpret_cast<__half2*>(dst + i + 2) = __floats2half2_rn(v.z, v.w);
    }
}

__global__ void final_layer(const __half* __restrict__ h, const float* __restrict__ w3,
                            const float* __restrict__ b3, float* __restrict__ out)
{
    __shared__ float sw[U3 * ACT];
    __shared__ float sbb[ACT];
    const int tid = threadIdx.x;
    for (int i = tid; i < U3 * ACT; i += blockDim.x) sw[i] = w3[i];
    if (tid < ACT) sbb[tid] = b3[tid];
    __syncthreads();
    const int wid = tid >> 5, lane = tid & 31;
    const int row = blockIdx.x * (blockDim.x >> 5) + wid;
    const __half* hr = h + (size_t)row * U3;
    float acc[ACT] = {0.f, 0.f, 0.f, 0.f, 0.f, 0.f};
    for (int k0 = lane * 2; k0 < U3; k0 += 64) {
        __half2 hv = *reinterpret_cast<const __half2*>(hr + k0);
        float x0 = __half2float(hv.x), x1 = __half2float(hv.y);
        #pragma unroll
        for (int n = 0; n < ACT; n++)
            acc[n] += x0 * sw[k0 * ACT + n] + x1 * sw[(k0 + 1) * ACT + n];
    }
    #pragma unroll
    for (int n = 0; n < ACT; n++)
        #pragma unroll
        for (int off = 16; off; off >>= 1)
            acc[n] += __shfl_xor_sync(0xffffffffu, acc[n], off);
    if (lane < ACT) out[(size_t)row * ACT + lane] = fmaxf(acc[lane] + sbb[lane], 0.f);
}

// ===================== launch =====================
extern "C" void kernel_launch(void* const* d_in, const int* in_sizes, int n_in,
                              void* d_out, int out_size)
{
    const float* x        = (const float*)d_in[0];
    const float* gpe_mask = (const float*)d_in[1];
    const float* gpe_w    = (const float*)d_in[2];
    const float* gpe_b    = (const float*)d_in[3];
    const float* gpi_mask = (const float*)d_in[4];
    const float* gpi_w    = (const float*)d_in[5];
    const float* gpi_b    = (const float*)d_in[6];
    const float* w1       = (const float*)d_in[7];
    const float* b1       = (const float*)d_in[8];
    const float* w2       = (const float*)d_in[9];
    const float* b2       = (const float*)d_in[10];
    const float* w3       = (const float*)d_in[11];
    const float* b3       = (const float*)d_in[12];
    float* out = (float*)d_out;

    __half *xh, *wt_gpi, *wm_gpe, *weffs, *w1s, *wfull_h, *wt_w2, *h1, *h2;
    float *wx32, *wf_p0, *wf_p1, *wf_p2, *bias_eff, *bias_full;
    cudaGetSymbolAddress((void**)&xh,        g_xh);
    cudaGetSymbolAddress((void**)&wt_gpi,    g_wt_gpi);
    cudaGetSymbolAddress((void**)&wm_gpe,    g_wm_gpe);
    cudaGetSymbolAddress((void**)&wx32,      g_wx32);
    cudaGetSymbolAddress((void**)&weffs,     g_weffs);
    cudaGetSymbolAddress((void**)&w1s,       g_w1s);
    cudaGetSymbolAddress((void**)&wf_p0,     g_wf_p0);
    cudaGetSymbolAddress((void**)&wf_p1,     g_wf_p1);
    cudaGetSymbolAddress((void**)&wf_p2,     g_wf_p2);
    cudaGetSymbolAddress((void**)&wfull_h,   g_wfull_h);
    cudaGetSymbolAddress((void**)&bias_eff,  g_bias_eff);
    cudaGetSymbolAddress((void**)&bias_full, g_bias_full);
    cudaGetSymbolAddress((void**)&wt_w2,     g_wt_w2);
    cudaGetSymbolAddress((void**)&h1,        g_h1);
    cudaGetSymbolAddress((void**)&h2,        g_h2);

    cudaFuncSetAttribute(gemm_f16, cudaFuncAttributeMaxDynamicSharedMemorySize, SMEM_TOTAL);

    static cudaStream_t sA = nullptr, sB = nullptr, sC = nullptr;
    static cudaEvent_t evRoot, evGpi, evWx, evW1s, evW2, evWeff, evP1, evP2, evWfull, evBias;
    if (sA == nullptr) {
        cudaStreamCreateWithFlags(&sA, cudaStreamNonBlocking);
        cudaStreamCreateWithFlags(&sB, cudaStreamNonBlocking);
        cudaStreamCreateWithFlags(&sC, cudaStreamNonBlocking);
        cudaEventCreateWithFlags(&evRoot,  cudaEventDisableTiming);
        cudaEventCreateWithFlags(&evGpi,   cudaEventDisableTiming);
        cudaEventCreateWithFlags(&evWx,    cudaEventDisableTiming);
        cudaEventCreateWithFlags(&evW1s,   cudaEventDisableTiming);
        cudaEventCreateWithFlags(&evW2,    cudaEventDisableTiming);
        cudaEventCreateWithFlags(&evWeff,  cudaEventDisableTiming);
        cudaEventCreateWithFlags(&evP1,    cudaEventDisableTiming);
        cudaEventCreateWithFlags(&evP2,    cudaEventDisableTiming);
        cudaEventCreateWithFlags(&evWfull, cudaEventDisableTiming);
        cudaEventCreateWithFlags(&evBias,  cudaEventDisableTiming);
    }

    const dim3 tb(32, 8);
    const int nx = BATCH * DGPE_IN;

    // ---- fork ----
    cudaEventRecord(evRoot, 0);
    cudaStreamWaitEvent(sA, evRoot, 0);
    cudaStreamWaitEvent(sB, evRoot, 0);
    cudaStreamWaitEvent(sC, evRoot, 0);

    // L: the big independent x conversion, overlapped with all prep
    convert_f2h<<<(nx / 4 + 255) / 256, 256>>>(x, xh, nx);

    // sA: gpi transpose FIRST (feeds W_eff), then off-path bias chain
    transpose_mask<<<dim3(DGPI_IN / 32, DGPI_OUT / 32), tb, 0, sA>>>(gpi_w, gpi_mask, wt_gpi, DGPI_IN, DGPI_OUT);
    cudaEventRecord(evGpi, sA);
    bias_eff_kernel<<<DGPI_OUT / 8, 256, 0, sA>>>(gpi_w, gpi_mask, gpe_b, gpi_b, bias_eff);
    bias_full_kernel<<<U3 / 8, 256, 0, sA>>>(bias_eff, w1, b1, bias_full);
    cudaEventRecord(evBias, sA);

    // sC: wx32, w1 split, w2 transpose
    mask_apply_nt_f32<<<dim3(DGPI_OUT / 32, DGPE_IN / 32), tb, 0, sC>>>(gpi_w, gpi_mask, DGPI_IN, wx32, DGPI_OUT);
    cudaEventRecord(evWx, sC);
    transpose_split_w1<<<dim3(DGPI_OUT / 32, U3 / 32), tb, 0, sC>>>(w1, w1s, DGPI_OUT, U3);
    cudaEventRecord(evW1s, sC);
    transpose_mask<<<dim3(U3 / 32, U3 / 32), tb, 0, sC>>>(w2, nullptr, wt_w2, U3, U3);
    cudaEventRecord(evW2, sC);

    // sB: gpe mask -> W_eff GEMM (writes hi|hi|lo 3-seg directly via out_mode=2)
    mask_apply_nt<<<dim3(DGPE_OUT / 32, DGPE_IN / 32), tb, 0, sB>>>(gpe_w, gpe_mask, DGPE_IN, wm_gpe, DGPE_OUT);
    cudaStreamWaitEvent(sB, evGpi, 0);
    cudaStreamWaitEvent(sB, evWx, 0);
    gemm_f16<<<dim3(DGPI_OUT / BN, DGPE_IN / BM), NTHREADS, SMEM_TOTAL, sB>>>(
        wm_gpe, wm_gpe, DGPE_OUT, DGPE_OUT, DGPE_OUT,
        wt_gpi + DGPE_IN, DGPI_IN, nullptr,
        wx32, DGPI_OUT, 2, weffs, 2, DGPI_OUT, DGPE_OUT, 0);
    cudaEventRecord(evWeff, sB);

    // W_full split-K: 3 concurrent K=1536 GEMMs (fp32 partials), then reduce
    // seg0: w1hi x weff_hi   (sB)
    cudaStreamWaitEvent(sB, evW1s, 0);
    gemm_f16<<<dim3(DGPE_IN / BN, U3 / BM), NTHREADS, SMEM_TOTAL, sB>>>(
        w1s, w1s, DGPI_OUT, 2 * DGPI_OUT, 2 * DGPI_OUT,
        weffs, 3 * DGPI_OUT, nullptr,
        nullptr, 0, 0, wf_p0, 1, DGPE_IN, DGPI_OUT, 0);
    // seg1: w1lo x weff_hi   (sA)
    cudaStreamWaitEvent(sA, evWeff, 0);
    cudaStreamWaitEvent(sA, evW1s, 0);
    gemm_f16<<<dim3(DGPE_IN / BN, U3 / BM), NTHREADS, SMEM_TOTAL, sA>>>(
        w1s + DGPI_OUT, w1s + DGPI_OUT, DGPI_OUT, 2 * DGPI_OUT, 2 * DGPI_OUT,
        weffs + DGPI_OUT, 3 * DGPI_OUT, nullptr,
        nullptr, 0, 0, wf_p1, 1, DGPE_IN, DGPI_OUT, 0);
    cudaEventRecord(evP1, sA);
    // seg2: w1hi x weff_lo   (sC)
    cudaStreamWaitEvent(sC, evWeff, 0);
    gemm_f16<<<dim3(DGPE_IN / BN, U3 / BM), NTHREADS, SMEM_TOTAL, sC>>>(
        w1s, w1s, DGPI_OUT, 2 * DGPI_OUT, 2 * DGPI_OUT,
        weffs + 2 * DGPI_OUT, 3 * DGPI_OUT, nullptr,
        nullptr, 0, 0, wf_p2, 1, DGPE_IN, DGPI_OUT, 0);
    cudaEventRecord(evP2, sC);
    // reduce on sB
    cudaStreamWaitEvent(sB, evP1, 0);
    cudaStreamWaitEvent(sB, evP2, 0);
    reduce3_f16<<<(U3 * DGPE_IN / 4) / 256, 256, 0, sB>>>(wf_p0, wf_p1, wf_p2, wfull_h);
    cudaEventRecord(evWfull, sB);

    // ---- join ----
    cudaStreamWaitEvent(0, evWfull, 0);
    cudaStreamWaitEvent(0, evBias, 0);
    cudaStreamWaitEvent(0, evW2, 0);

    // h1 = relu(x @ W_full + bias_full)   (25.8 GF)
    gemm_f16<<<dim3(U3 / BN, BATCH / BM), NTHREADS, SMEM_TOTAL>>>(
        xh, xh, DGPE_IN, DGPE_IN, DGPE_IN,
        wfull_h, DGPE_IN, bias_full,
        nullptr, 0, 0, h1, 0, U3, DGPE_IN, 1);
    // h2 = relu(h1 @ w2 + b2)   (8.6 GF)
    gemm_f16<<<dim3(U3 / BN, BATCH / BM), NTHREADS, SMEM_TOTAL>>>(
        h1, h1, U3, U3, U3,
        wt_w2, U3, b2,
        nullptr, 0, 0, h2, 0, U3, U3, 1);
    // out = relu(h2 @ w3 + b3)
    final_layer<<<BATCH / 8, 256>>>(h2, w3, b3, out);
}

// round 12
// speedup vs baseline: 1.2296x; 1.0556x over previous
#include <cuda_runtime.h>
#include <cuda_fp16.h>
#include <cstdint>

// ===================== problem dims =====================
static constexpr int BATCH    = 16384;
static constexpr int DGPE_IN  = 1536;
static constexpr int DGPE_OUT = 1536;
static constexpr int DGPI_IN  = 3072;
static constexpr int DGPI_OUT = 1536;
static constexpr int U3       = 512;
static constexpr int ACT      = 6;

// ===================== device scratch (no cudaMalloc allowed) =====================
__device__ __half g_xh     [(size_t)BATCH * DGPE_IN];        // x as fp16
__device__ __half g_wt_gpiB[DGPI_OUT * DGPE_OUT];            // [j][k] masked Wg^T (gpi cols 1536:3072)
__device__ __half g_wm_gpe [DGPE_IN * DGPE_OUT];             // [i][k] masked gpe W (non-transposed)
__device__ float  g_wx32   [DGPE_IN * DGPI_OUT];             // [i][j] masked Wx (fp32, exact)
__device__ __half g_weffs  [(size_t)DGPE_IN * 3 * DGPI_OUT]; // [i][ hi | hi | lo ]
__device__ __half g_w1s    [U3 * 2 * DGPI_OUT];              // [n][ hi | lo ]
__device__ float  g_wf_p0  [U3 * DGPE_IN];                   // W_full partials (fp32)
__device__ float  g_wf_p1  [U3 * DGPE_IN];
__device__ float  g_wf_p2  [U3 * DGPE_IN];
__device__ __half g_wfull_h[U3 * DGPE_IN];                   // [n][i] fp16 final
__device__ float  g_bias_eff[DGPI_OUT];
__device__ float  g_bias_full[U3];
__device__ __half g_wt_w2  [U3 * U3];
__device__ __half g_h1[(size_t)BATCH * U3];
__device__ float  g_pb[(size_t)4 * BATCH * 8];               // fused-out partials

// ===================== helpers =====================
__device__ __forceinline__ uint32_t smem_u32(const void* p) {
    return (uint32_t)__cvta_generic_to_shared(p);
}
#define CP_ASYNC16(dst, src) \
    asm volatile("cp.async.cg.shared.global [%0], [%1], 16;\n" :: "r"(dst), "l"(src))
#define CP_ASYNC_COMMIT() asm volatile("cp.async.commit_group;\n" ::: "memory")
#define CP_ASYNC_WAIT(n)  asm volatile("cp.async.wait_group %0;\n" :: "n"(n) : "memory")

__device__ __forceinline__ uint32_t swz64(uint32_t byte_off) {
    return byte_off ^ ((byte_off >> 3) & 0x30);
}

__device__ __forceinline__ void ldmatrix_x4(uint32_t r[4], uint32_t addr) {
    asm volatile("ldmatrix.sync.aligned.m8n8.x4.shared.b16 {%0,%1,%2,%3}, [%4];"
                 : "=r"(r[0]), "=r"(r[1]), "=r"(r[2]), "=r"(r[3]) : "r"(addr));
}

__device__ __forceinline__ void mma_f16(float c[4], const uint32_t a[4],
                                        uint32_t b0, uint32_t b1) {
    asm volatile(
        "mma.sync.aligned.m16n8k16.row.col.f32.f16.f16.f32 "
        "{%0,%1,%2,%3}, {%4,%5,%6,%7}, {%8,%9}, {%0,%1,%2,%3};"
        : "+f"(c[0]), "+f"(c[1]), "+f"(c[2]), "+f"(c[3])
        : "r"(a[0]), "r"(a[1]), "r"(a[2]), "r"(a[3]), "r"(b0), "r"(b1));
}

// ===================== GEMM config =====================
static constexpr int BM = 128, BN = 128, BK = 32, STAGES = 4, NTHREADS = 256;
static constexpr int A_STAGE_BYTES = BM * BK * 2;
static constexpr int B_STAGE_BYTES = BN * BK * 2;
static constexpr int STAGE_BYTES   = A_STAGE_BYTES + B_STAGE_BYTES;
static constexpr int SMEM_BIAS     = 0;       // 128 floats
static constexpr int SMEM_W3      = 512;      // 128*6 floats (fused kernel only)
static constexpr int SMEM_TILES    = 4096;
static constexpr int SMEM_TOTAL    = SMEM_TILES + STAGES * STAGE_BYTES; // 69632

// D[m,n] = sum_k A[m,k] * BT[n*ldb + k] (+ bias[n]) (+ Cadd) (optional ReLU)
// out_mode: 0 = fp16 D (ld N), 1 = fp32 D (ld N),
//           2 = fp16 3-seg hi|hi|lo (ld 3N).
// cadd_mode: 0 none, 1 fp16, 2 fp32.
// A K-split: k < ksplit -> A0 (lda0) else A1 (lda1, k-ksplit). ksplit % BK == 0.
__global__ void __launch_bounds__(NTHREADS, 2)
gemm_f16(const __half* __restrict__ A0, const __half* __restrict__ A1,
         int ksplit, int lda0, int lda1,
         const __half* __restrict__ BT, int ldb, const float* __restrict__ bias,
         const void* __restrict__ Cadd, int ldc, int cadd_mode,
         void* __restrict__ D, int out_mode, int N, int K, int do_relu)
{
    extern __shared__ char smem[];
    float* sb_bias = (float*)(smem + SMEM_BIAS);
    const uint32_t stile = smem_u32(smem) + SMEM_TILES;
    const int tid  = threadIdx.x;
    const int wid  = tid >> 5;
    const int lane = tid & 31;
    const int g    = lane >> 2;
    const int t    = lane & 3;
    const int m0 = blockIdx.y * BM;
    const int n0 = blockIdx.x * BN;
    const int warp_m = (wid >> 2) * 64;
    const int warp_n = (wid & 3) * 32;

    if (tid < BN) sb_bias[tid] = bias ? bias[n0 + tid] : 0.f;

    const int KB = K / BK;

    auto load_stage = [&](int kb) {
        const int s = kb & (STAGES - 1);
        const int k0 = kb * BK;
        const uint32_t a_base = stile + s * STAGE_BYTES;
        const uint32_t b_base = a_base + A_STAGE_BYTES;
        #pragma unroll
        for (int j = 0; j < 2; j++) {
            int idx = tid + j * NTHREADS;
            int row = idx >> 2;
            int c   = idx & 3;
            int kg  = k0 + (c << 3);
            const __half* src = (kg < ksplit)
                ? (A0 + (size_t)(m0 + row) * lda0 + kg)
                : (A1 + (size_t)(m0 + row) * lda1 + (kg - ksplit));
            uint32_t dst = a_base + swz64((uint32_t)(row * 64 + (c << 4)));
            CP_ASYNC16(dst, src);
        }
        #pragma unroll
        for (int j = 0; j < 2; j++) {
            int idx = tid + j * NTHREADS;
            int row = idx >> 2;
            int c   = idx & 3;
            const __half* src = BT + (size_t)(n0 + row) * ldb + k0 + (c << 3);
            uint32_t dst = b_base + swz64((uint32_t)(row * 64 + (c << 4)));
            CP_ASYNC16(dst, src);
        }
        CP_ASYNC_COMMIT();
    };

    float acc[4][4][4];
    #pragma unroll
    for (int mt = 0; mt < 4; mt++)
        #pragma unroll
        for (int nt = 0; nt < 4; nt++)
            #pragma unroll
            for (int r = 0; r < 4; r++) acc[mt][nt][r] = 0.f;

    const int lm_row = (lane & 8) + (lane & 7);
    const int lm_k   = (lane & 16) >> 1;

    load_stage(0); load_stage(1); load_stage(2);

    for (int kb = 0; kb < KB; kb++) {
        if (kb < KB - 3) { CP_ASYNC_WAIT(2); } else { CP_ASYNC_WAIT(0); }
        __syncthreads();
        if (kb + 3 < KB) load_stage(kb + 3);

        const int s = kb & (STAGES - 1);
        const uint32_t As = stile + s * STAGE_BYTES;
        const uint32_t Bs = As + A_STAGE_BYTES;

        #pragma unroll
        for (int ks = 0; ks < 2; ks++) {
            const int kk = ks * 16;
            uint32_t am[4][4], bm[2][4];
            #pragma unroll
            for (int mt = 0; mt < 4; mt++) {
                int row = warp_m + mt * 16 + lm_row;
                ldmatrix_x4(am[mt], As + swz64((uint32_t)(row * 64 + (kk + lm_k) * 2)));
            }
            #pragma unroll
            for (int pr = 0; pr < 2; pr++) {
                int row = warp_n + pr * 16 + lm_row;
                ldmatrix_x4(bm[pr], Bs + swz64((uint32_t)(row * 64 + (kk + lm_k) * 2)));
            }
            #pragma unroll
            for (int mt = 0; mt < 4; mt++)
                #pragma unroll
                for (int nt = 0; nt < 4; nt++)
                    mma_f16(acc[mt][nt], am[mt], bm[nt >> 1][nt & 1], bm[nt >> 1][(nt & 1) + 2]);
        }
    }

    // epilogue
    #pragma unroll
    for (int mt = 0; mt < 4; mt++) {
        const int row = m0 + warp_m + mt * 16 + g;
        #pragma unroll
        for (int nt = 0; nt < 4; nt++) {
            const int cb = warp_n + nt * 8 + t * 2;
            const int col = n0 + cb;
            float b0 = sb_bias[cb], b1 = sb_bias[cb + 1];
            float2 v0 = make_float2(acc[mt][nt][0] + b0, acc[mt][nt][1] + b1);
            float2 v1 = make_float2(acc[mt][nt][2] + b0, acc[mt][nt][3] + b1);
            if (cadd_mode == 1) {
                const __half* C = (const __half*)Cadd;
                __half2 c0 = *reinterpret_cast<const __half2*>(C + (size_t)row * ldc + col);
                __half2 c1 = *reinterpret_cast<const __half2*>(C + (size_t)(row + 8) * ldc + col);
                v0.x += __half2float(c0.x); v0.y += __half2float(c0.y);
                v1.x += __half2float(c1.x); v1.y += __half2float(c1.y);
            } else if (cadd_mode == 2) {
                const float* C = (const float*)Cadd;
                float2 c0 = *reinterpret_cast<const float2*>(C + (size_t)row * ldc + col);
                float2 c1 = *reinterpret_cast<const float2*>(C + (size_t)(row + 8) * ldc + col);
                v0.x += c0.x; v0.y += c0.y;
                v1.x += c1.x; v1.y += c1.y;
            }
            if (do_relu) {
                v0.x = fmaxf(v0.x, 0.f); v0.y = fmaxf(v0.y, 0.f);
                v1.x = fmaxf(v1.x, 0.f); v1.y = fmaxf(v1.y, 0.f);
            }
            if (out_mode == 0) {
                __half* Dh = (__half*)D;
                *reinterpret_cast<__half2*>(Dh + (size_t)row * N + col)       = __floats2half2_rn(v0.x, v0.y);
                *reinterpret_cast<__half2*>(Dh + (size_t)(row + 8) * N + col) = __floats2half2_rn(v1.x, v1.y);
            } else if (out_mode == 1) {
                float* Df = (float*)D;
                *reinterpret_cast<float2*>(Df + (size_t)row * N + col)       = v0;
                *reinterpret_cast<float2*>(Df + (size_t)(row + 8) * N + col) = v1;
            } else {
                __half* Dh = (__half*)D;
                __half2 h0 = __floats2half2_rn(v0.x, v0.y);
                __half2 h1v = __floats2half2_rn(v1.x, v1.y);
                __half2 l0 = __floats2half2_rn(v0.x - __half2float(h0.x),
                                               v0.y - __half2float(h0.y));
                __half2 l1 = __floats2half2_rn(v1.x - __half2float(h1v.x),
                                               v1.y - __half2float(h1v.y));
                size_t base0 = (size_t)row * (3 * N);
                size_t base1 = (size_t)(row + 8) * (3 * N);
                *reinterpret_cast<__half2*>(Dh + base0 + col)         = h0;
                *reinterpret_cast<__half2*>(Dh + base0 + N + col)     = h0;
                *reinterpret_cast<__half2*>(Dh + base0 + 2 * N + col) = l0;
                *reinterpret_cast<__half2*>(Dh + base1 + col)         = h1v;
                *reinterpret_cast<__half2*>(Dh + base1 + N + col)     = h1v;
                *reinterpret_cast<__half2*>(Dh + base1 + 2 * N + col) = l1;
            }
        }
    }
}

// ============ fused h2+final: pb[bx][m][0:6] = relu(h1@w2+b2)[m, n0:n0+128] @ w3[n0:n0+128] ====
__global__ void __launch_bounds__(NTHREADS, 2)
gemm_h2_fused(const __half* __restrict__ A, const __half* __restrict__ BT,
              const float* __restrict__ bias, const float* __restrict__ w3,
              float* __restrict__ pb)
{
    extern __shared__ char smem[];
    float* sb_bias = (float*)(smem + SMEM_BIAS);
    float* w3s     = (float*)(smem + SMEM_W3);     // [128][6]
    const uint32_t stile = smem_u32(smem) + SMEM_TILES;
    const int tid  = threadIdx.x;
    const int wid  = tid >> 5;
    const int lane = tid & 31;
    const int g    = lane >> 2;
    const int t    = lane & 3;
    const int m0 = blockIdx.y * BM;
    const int n0 = blockIdx.x * BN;
    const int warp_m = (wid >> 2) * 64;
    const int warp_n = (wid & 3) * 32;
    const int K = U3, ldab = U3;

    if (tid < BN) sb_bias[tid] = bias[n0 + tid];
    for (int i = tid; i < BN * ACT; i += NTHREADS)
        w3s[i] = w3[(size_t)(n0 + i / ACT) * ACT + (i % ACT)];

    const int KB = K / BK;   // 16

    auto load_stage = [&](int kb) {
        const int s = kb & (STAGES - 1);
        const int k0 = kb * BK;
        const uint32_t a_base = stile + s * STAGE_BYTES;
        const uint32_t b_base = a_base + A_STAGE_BYTES;
        #pragma unroll
        for (int j = 0; j < 2; j++) {
            int idx = tid + j * NTHREADS;
            int row = idx >> 2;
            int c   = idx & 3;
            const __half* src = A + (size_t)(m0 + row) * ldab + k0 + (c << 3);
            uint32_t dst = a_base + swz64((uint32_t)(row * 64 + (c << 4)));
            CP_ASYNC16(dst, src);
        }
        #pragma unroll
        for (int j = 0; j < 2; j++) {
            int idx = tid + j * NTHREADS;
            int row = idx >> 2;
            int c   = idx & 3;
            const __half* src = BT + (size_t)(n0 + row) * ldab + k0 + (c << 3);
            uint32_t dst = b_base + swz64((uint32_t)(row * 64 + (c << 4)));
            CP_ASYNC16(dst, src);
        }
        CP_ASYNC_COMMIT();
    };

    float acc[4][4][4];
    #pragma unroll
    for (int mt = 0; mt < 4; mt++)
        #pragma unroll
        for (int nt = 0; nt < 4; nt++)
            #pragma unroll
            for (int r = 0; r < 4; r++) acc[mt][nt][r] = 0.f;

    const int lm_row = (lane & 8) + (lane & 7);
    const int lm_k   = (lane & 16) >> 1;

    load_stage(0); load_stage(1); load_stage(2);

    for (int kb = 0; kb < KB; kb++) {
        if (kb < KB - 3) { CP_ASYNC_WAIT(2); } else { CP_ASYNC_WAIT(0); }
        __syncthreads();
        if (kb + 3 < KB) load_stage(kb + 3);

        const int s = kb & (STAGES - 1);
        const uint32_t As = stile + s * STAGE_BYTES;
        const uint32_t Bs = As + A_STAGE_BYTES;

        #pragma unroll
        for (int ks = 0; ks < 2; ks++) {
            const int kk = ks * 16;
            uint32_t am[4][4], bm[2][4];
            #pragma unroll
            for (int mt = 0; mt < 4; mt++) {
                int row = warp_m + mt * 16 + lm_row;
                ldmatrix_x4(am[mt], As + swz64((uint32_t)(row * 64 + (kk + lm_k) * 2)));
            }
            #pragma unroll
            for (int pr = 0; pr < 2; pr++) {
                int row = warp_n + pr * 16 + lm_row;
                ldmatrix_x4(bm[pr], Bs + swz64((uint32_t)(row * 64 + (kk + lm_k) * 2)));
            }
            #pragma unroll
            for (int mt = 0; mt < 4; mt++)
                #pragma unroll
                for (int nt = 0; nt < 4; nt++)
                    mma_f16(acc[mt][nt], am[mt], bm[nt >> 1][nt & 1], bm[nt >> 1][(nt & 1) + 2]);
        }
    }

    // fused epilogue: v = relu(acc + bias); P[row][n] += v * w3s  (deterministic)
    float* Pw = (float*)(smem + SMEM_TILES);   // [4][128][6], reuses tile region
    __syncthreads();
    #pragma unroll
    for (int mt = 0; mt < 4; mt++) {
        float s0[ACT] = {0,0,0,0,0,0}, s1[ACT] = {0,0,0,0,0,0};
        #pragma unroll
        for (int nt = 0; nt < 4; nt++) {
            const int cb = warp_n + nt * 8 + t * 2;
            float b0 = sb_bias[cb], b1v = sb_bias[cb + 1];
            float v00 = fmaxf(acc[mt][nt][0] + b0,  0.f);
            float v01 = fmaxf(acc[mt][nt][1] + b1v, 0.f);
            float v10 = fmaxf(acc[mt][nt][2] + b0,  0.f);
            float v11 = fmaxf(acc[mt][nt][3] + b1v, 0.f);
            #pragma unroll
            for (int n = 0; n < ACT; n++) {
                float w0 = w3s[cb * ACT + n], w1v = w3s[(cb + 1) * ACT + n];
                s0[n] += v00 * w0 + v01 * w1v;
                s1[n] += v10 * w0 + v11 * w1v;
            }
        }
        #pragma unroll
        for (int n = 0; n < ACT; n++) {
            s0[n] += __shfl_xor_sync(0xffffffffu, s0[n], 1);
            s0[n] += __shfl_xor_sync(0xffffffffu, s0[n], 2);
            s1[n] += __shfl_xor_sync(0xffffffffu, s1[n], 1);
            s1[n] += __shfl_xor_sync(0xffffffffu, s1[n], 2);
        }
        if (t == 0) {
            const int wn = wid & 3;
            const int rl = warp_m + mt * 16 + g;
            #pragma unroll
            for (int n = 0; n < ACT; n++) {
                Pw[(wn * 128 + rl) * ACT + n]     = s0[n];
                Pw[(wn * 128 + rl + 8) * ACT + n] = s1[n];
            }
        }
    }
    __syncthreads();
    if (tid < 128) {
        #pragma unroll
        for (int n = 0; n < ACT; n++) {
            float s = Pw[(0 * 128 + tid) * ACT + n] + Pw[(1 * 128 + tid) * ACT + n]
                    + Pw[(2 * 128 + tid) * ACT + n] + Pw[(3 * 128 + tid) * ACT + n];
            pb[((size_t)blockIdx.x * BATCH + m0 + tid) * 8 + n] = s;
        }
    }
}

// out[m][n] = relu(b3[n] + sum_bx pb[bx][m][n])
__global__ void combine_out(const float* __restrict__ pb, const float* __restrict__ b3,
                            float* __restrict__ out)
{
    int idx = blockIdx.x * blockDim.x + threadIdx.x;   // over BATCH*ACT
    if (idx >= BATCH * ACT) return;
    int m = idx / ACT, n = idx % ACT;
    float s = b3[n];
    #pragma unroll
    for (int bx = 0; bx < 4; bx++)
        s += pb[((size_t)bx * BATCH + m) * 8 + n];
    out[(size_t)m * ACT + n] = fmaxf(s, 0.f);
}

// ===================== weight prep kernels =====================
// wt[n][k] = f16(w[k][n] * mask[n*mask_ld + mask_koff + k])
__global__ void transpose_mask(const float* __restrict__ w, const float* __restrict__ mask,
                               __half* __restrict__ wt, int K, int N, int mask_ld, int mask_koff)
{
    __shared__ float tile[32][33];
    const int k0 = blockIdx.x * 32, n0 = blockIdx.y * 32;
    const int tx = threadIdx.x, ty = threadIdx.y;
    #pragma unroll
    for (int j = 0; j < 32; j += 8)
        tile[ty + j][tx] = w[(size_t)(k0 + ty + j) * N + n0 + tx];
    __syncthreads();
    #pragma unroll
    for (int j = 0; j < 32; j += 8) {
        const int n = n0 + ty + j, k = k0 + tx;
        float v = tile[tx][ty + j];
        if (mask) v *= mask[(size_t)n * mask_ld + mask_koff + k];
        wt[(size_t)n * K + k] = __float2half_rn(v);
    }
}

__global__ void transpose_split_w1(const float* __restrict__ w, __half* __restrict__ w1s,
                                   int K, int N)
{
    __shared__ float tile[32][33];
    const int k0 = blockIdx.x * 32, n0 = blockIdx.y * 32;
    const int tx = threadIdx.x, ty = threadIdx.y;
    #pragma unroll
    for (int j = 0; j < 32; j += 8)
        tile[ty + j][tx] = w[(size_t)(k0 + ty + j) * N + n0 + tx];
    __syncthreads();
    #pragma unroll
    for (int j = 0; j < 32; j += 8) {
        const int n = n0 + ty + j, k = k0 + tx;
        float v = tile[tx][ty + j];
        __half hi = __float2half_rn(v);
        __half lo = __float2half_rn(v - __half2float(hi));
        w1s[(size_t)n * (2 * K) + k]     = hi;
        w1s[(size_t)n * (2 * K) + K + k] = lo;
    }
}

__global__ void mask_apply_nt(const float* __restrict__ w, const float* __restrict__ mask,
                              int mstride, __half* __restrict__ out, int J)
{
    __shared__ float mt[32][33];
    const int i0 = blockIdx.y * 32, j0 = blockIdx.x * 32;
    const int tx = threadIdx.x, ty = threadIdx.y;
    #pragma unroll
    for (int jj = 0; jj < 32; jj += 8)
        mt[ty + jj][tx] = mask[(size_t)(j0 + ty + jj) * mstride + i0 + tx];
    __syncthreads();
    #pragma unroll
    for (int jj = 0; jj < 32; jj += 8) {
        const int i = i0 + ty + jj, j = j0 + tx;
        out[(size_t)i * J + j] = __float2half_rn(w[(size_t)i * J + j] * mt[tx][ty + jj]);
    }
}

__global__ void mask_apply_nt_f32(const float* __restrict__ w, const float* __restrict__ mask,
                                  int mstride, float* __restrict__ out, int J)
{
    __shared__ float mt[32][33];
    const int i0 = blockIdx.y * 32, j0 = blockIdx.x * 32;
    const int tx = threadIdx.x, ty = threadIdx.y;
    #pragma unroll
    for (int jj = 0; jj < 32; jj += 8)
        mt[ty + jj][tx] = mask[(size_t)(j0 + ty + jj) * mstride + i0 + tx];
    __syncthreads();
    #pragma unroll
    for (int jj = 0; jj < 32; jj += 8) {
        const int i = i0 + ty + jj, j = j0 + tx;
        out[(size_t)i * J + j] = w[(size_t)i * J + j] * mt[tx][ty + jj];
    }
}

__global__ void reduce3_f16(const float* __restrict__ p0, const float* __restrict__ p1,
                            const float* __restrict__ p2, __half* __restrict__ out)
{
    int i = (blockIdx.x * blockDim.x + threadIdx.x) * 4;
    float4 a = *reinterpret_cast<const float4*>(p0 + i);
    float4 b = *reinterpret_cast<const float4*>(p1 + i);
    float4 c = *reinterpret_cast<const float4*>(p2 + i);
    *reinterpret_cast<__half2*>(out + i)     = __floats2half2_rn(a.x + b.x + c.x, a.y + b.y + c.y);
    *reinterpret_cast<__half2*>(out + i + 2) = __floats2half2_rn(a.z + b.z + c.z, a.w + b.w + c.w);
}

__global__ void bias_eff_kernel(const float* __restrict__ gpi_w, const float* __restrict__ gpi_mask,
                                const float* __restrict__ gpe_b,
                                const float* __restrict__ gpi_b, float* __restrict__ be)
{
    const int n = blockIdx.x * 8 + (threadIdx.x >> 5);
    const int lane = threadIdx.x & 31;
    const float* mrow = gpi_mask + (size_t)n * DGPI_IN + DGPE_IN;
    float s0 = 0.f, s1 = 0.f;
    for (int j = lane; j < DGPE_OUT; j += 64) {
        s0 += gpi_w[(size_t)(DGPE_IN + j) * DGPI_OUT + n] * mrow[j] * gpe_b[j];
        int j2 = j + 32;
        s1 += gpi_w[(size_t)(DGPE_IN + j2) * DGPI_OUT + n] * mrow[j2] * gpe_b[j2];
    }
    float s = s0 + s1;
    #pragma unroll
    for (int off = 16; off; off >>= 1) s += __shfl_xor_sync(0xffffffffu, s, off);
    if (lane == 0) be[n] = gpi_b[n] + s;
}

__global__ void bias_full_kernel(const float* __restrict__ be, const float* __restrict__ w1,
                                 const float* __restrict__ b1, float* __restrict__ bf)
{
    const int n = blockIdx.x * 8 + (threadIdx.x >> 5);
    const int lane = threadIdx.x & 31;
    float s0 = 0.f, s1 = 0.f;
    for (int j = lane; j < DGPI_OUT; j += 64) {
        s0 += be[j] * w1[(size_t)j * U3 + n];
        s1 += be[j + 32] * w1[(size_t)(j + 32) * U3 + n];
    }
    float s = s0 + s1;
    #pragma unroll
    for (int off = 16; off; off >>= 1) s += __shfl_xor_sync(0xffffffffu, s, off);
    if (lane == 0) bf[n] = b1[n] + s;
}

__global__ void convert_f2h(const float* __restrict__ src, __half* __restrict__ dst, int n)
{
    int i = (blockIdx.x * blockDim.x + threadIdx.x) * 4;
    if (i < n) {
        float4 v = *reinterpret_cast<const float4*>(src + i);
        *reinterpret_cast<__half2*>(dst + i)     = __floats2half2_rn(v.x, v.y);
        *reinterpret_cast<__half2*>(dst + i + 2) = __floats2half2_rn(v.z, v.w);
    }
}

// ===================== launch =====================
extern "C" void kernel_launch(void* const* d_in, const int* in_sizes, int n_in,
                              void* d_out, int out_size)
{
    const float* x        = (const float*)d_in[0];
    const float* gpe_mask = (const float*)d_in[1];
    const float* gpe_w    = (const float*)d_in[2];
    const float* gpe_b    = (const float*)d_in[3];
    const float* gpi_mask = (const float*)d_in[4];
    const float* gpi_w    = (const float*)d_in[5];
    const float* gpi_b    = (const float*)d_in[6];
    const float* w1       = (const float*)d_in[7];
    const float* b1       = (const float*)d_in[8];
    const float* w2       = (const float*)d_in[9];
    const float* b2       = (const float*)d_in[10];
    const float* w3       = (const float*)d_in[11];
    const float* b3       = (const float*)d_in[12];
    float* out = (float*)d_out;

    __half *xh, *wt_gpiB, *wm_gpe, *weffs, *w1s, *wfull_h, *wt_w2, *h1;
    float *wx32, *wf_p0, *wf_p1, *wf_p2, *bias_eff, *bias_full, *pb;
    cudaGetSymbolAddress((void**)&xh,        g_xh);
    cudaGetSymbolAddress((void**)&wt_gpiB,   g_wt_gpiB);
    cudaGetSymbolAddress((void**)&wm_gpe,    g_wm_gpe);
    cudaGetSymbolAddress((void**)&wx32,      g_wx32);
    cudaGetSymbolAddress((void**)&weffs,     g_weffs);
    cudaGetSymbolAddress((void**)&w1s,       g_w1s);
    cudaGetSymbolAddress((void**)&wf_p0,     g_wf_p0);
    cudaGetSymbolAddress((void**)&wf_p1,     g_wf_p1);
    cudaGetSymbolAddress((void**)&wf_p2,     g_wf_p2);
    cudaGetSymbolAddress((void**)&wfull_h,   g_wfull_h);
    cudaGetSymbolAddress((void**)&bias_eff,  g_bias_eff);
    cudaGetSymbolAddress((void**)&bias_full, g_bias_full);
    cudaGetSymbolAddress((void**)&wt_w2,     g_wt_w2);
    cudaGetSymbolAddress((void**)&h1,        g_h1);
    cudaGetSymbolAddress((void**)&pb,        g_pb);

    cudaFuncSetAttribute(gemm_f16,      cudaFuncAttributeMaxDynamicSharedMemorySize, SMEM_TOTAL);
    cudaFuncSetAttribute(gemm_h2_fused, cudaFuncAttributeMaxDynamicSharedMemorySize, SMEM_TOTAL);

    static cudaStream_t sA = nullptr, sB = nullptr, sC = nullptr;
    static cudaEvent_t evRoot, evGpi, evWx, evW1s, evW2, evWeff, evP1, evP2, evWfull, evBias;
    if (sA == nullptr) {
        cudaStreamCreateWithFlags(&sA, cudaStreamNonBlocking);
        cudaStreamCreateWithFlags(&sB, cudaStreamNonBlocking);
        cudaStreamCreateWithFlags(&sC, cudaStreamNonBlocking);
        cudaEventCreateWithFlags(&evRoot,  cudaEventDisableTiming);
        cudaEventCreateWithFlags(&evGpi,   cudaEventDisableTiming);
        cudaEventCreateWithFlags(&evWx,    cudaEventDisableTiming);
        cudaEventCreateWithFlags(&evW1s,   cudaEventDisableTiming);
        cudaEventCreateWithFlags(&evW2,    cudaEventDisableTiming);
        cudaEventCreateWithFlags(&evWeff,  cudaEventDisableTiming);
        cudaEventCreateWithFlags(&evP1,    cudaEventDisableTiming);
        cudaEventCreateWithFlags(&evP2,    cudaEventDisableTiming);
        cudaEventCreateWithFlags(&evWfull, cudaEventDisableTiming);
        cudaEventCreateWithFlags(&evBias,  cudaEventDisableTiming);
    }

    const dim3 tb(32, 8);
    const int nx = BATCH * DGPE_IN;

    // ---- fork ----
    cudaEventRecord(evRoot, 0);
    cudaStreamWaitEvent(sA, evRoot, 0);
    cudaStreamWaitEvent(sB, evRoot, 0);
    cudaStreamWaitEvent(sC, evRoot, 0);

    // L: the big independent x conversion, overlapped with all prep
    convert_f2h<<<(nx / 4 + 255) / 256, 256>>>(x, xh, nx);

    // sA: HALF gpi transpose (only Wg block, cols 1536:3072) FIRST, then bias chain
    transpose_mask<<<dim3(DGPE_OUT / 32, DGPI_OUT / 32), tb, 0, sA>>>(
        gpi_w + (size_t)DGPE_IN * DGPI_OUT, gpi_mask, wt_gpiB,
        DGPE_OUT, DGPI_OUT, DGPI_IN, DGPE_IN);
    cudaEventRecord(evGpi, sA);
    bias_eff_kernel<<<DGPI_OUT / 8, 256, 0, sA>>>(gpi_w, gpi_mask, gpe_b, gpi_b, bias_eff);
    bias_full_kernel<<<U3 / 8, 256, 0, sA>>>(bias_eff, w1, b1, bias_full);
    cudaEventRecord(evBias, sA);

    // sC: wx32, w1 split, w2 transpose
    mask_apply_nt_f32<<<dim3(DGPI_OUT / 32, DGPE_IN / 32), tb, 0, sC>>>(gpi_w, gpi_mask, DGPI_IN, wx32, DGPI_OUT);
    cudaEventRecord(evWx, sC);
    transpose_split_w1<<<dim3(DGPI_OUT / 32, U3 / 32), tb, 0, sC>>>(w1, w1s, DGPI_OUT, U3);
    cudaEventRecord(evW1s, sC);
    transpose_mask<<<dim3(U3 / 32, U3 / 32), tb, 0, sC>>>(w2, nullptr, wt_w2, U3, U3, U3, 0);
    cudaEventRecord(evW2, sC);

    // sB: gpe mask -> W_eff GEMM (writes hi|hi|lo 3-seg directly)
    mask_apply_nt<<<dim3(DGPE_OUT / 32, DGPE_IN / 32), tb, 0, sB>>>(gpe_w, gpe_mask, DGPE_IN, wm_gpe, DGPE_OUT);
    cudaStreamWaitEvent(sB, evGpi, 0);
    cudaStreamWaitEvent(sB, evWx, 0);
    gemm_f16<<<dim3(DGPI_OUT / BN, DGPE_IN / BM), NTHREADS, SMEM_TOTAL, sB>>>(
        wm_gpe, wm_gpe, DGPE_OUT, DGPE_OUT, DGPE_OUT,
        wt_gpiB, DGPE_OUT, nullptr,
        wx32, DGPI_OUT, 2, weffs, 2, DGPI_OUT, DGPE_OUT, 0);
    cudaEventRecord(evWeff, sB);

    // W_full split-K: 3 concurrent K=1536 GEMMs (fp32 partials), then reduce
    cudaStreamWaitEvent(sB, evW1s, 0);
    gemm_f16<<<dim3(DGPE_IN / BN, U3 / BM), NTHREADS, SMEM_TOTAL, sB>>>(
        w1s, w1s, DGPI_OUT, 2 * DGPI_OUT, 2 * DGPI_OUT,
        weffs, 3 * DGPI_OUT, nullptr,
        nullptr, 0, 0, wf_p0, 1, DGPE_IN, DGPI_OUT, 0);
    cudaStreamWaitEvent(sA, evWeff, 0);
    cudaStreamWaitEvent(sA, evW1s, 0);
    gemm_f16<<<dim3(DGPE_IN / BN, U3 / BM), NTHREADS, SMEM_TOTAL, sA>>>(
        w1s + DGPI_OUT, w1s + DGPI_OUT, DGPI_OUT, 2 * DGPI_OUT, 2 * DGPI_OUT,
        weffs + DGPI_OUT, 3 * DGPI_OUT, nullptr,
        nullptr, 0, 0, wf_p1, 1, DGPE_IN, DGPI_OUT, 0);
    cudaEventRecord(evP1, sA);
    cudaStreamWaitEvent(sC, evWeff, 0);
    gemm_f16<<<dim3(DGPE_IN / BN, U3 / BM), NTHREADS, SMEM_TOTAL, sC>>>(
        w1s, w1s, DGPI_OUT, 2 * DGPI_OUT, 2 * DGPI_OUT,
        weffs + 2 * DGPI_OUT, 3 * DGPI_OUT, nullptr,
        nullptr, 0, 0, wf_p2, 1, DGPE_IN, DGPI_OUT, 0);
    cudaEventRecord(evP2, sC);
    cudaStreamWaitEvent(sB, evP1, 0);
    cudaStreamWaitEvent(sB, evP2, 0);
    reduce3_f16<<<(U3 * DGPE_IN / 4) / 256, 256, 0, sB>>>(wf_p0, wf_p1, wf_p2, wfull_h);
    cudaEventRecord(evWfull, sB);

    // ---- join ----
    cudaStreamWaitEvent(0, evWfull, 0);
    cudaStreamWaitEvent(0, evBias, 0);
    cudaStreamWaitEvent(0, evW2, 0);

    // h1 = relu(x @ W_full + bias_full)   (25.8 GF)
    gemm_f16<<<dim3(U3 / BN, BATCH / BM), NTHREADS, SMEM_TOTAL>>>(
        xh, xh, DGPE_IN, DGPE_IN, DGPE_IN,
        wfull_h, DGPE_IN, bias_full,
        nullptr, 0, 0, h1, 0, U3, DGPE_IN, 1);
    // fused: pb = relu(h1 @ w2 + b2) @ w3  (per n-block partials)
    gemm_h2_fused<<<dim3(U3 / BN, BATCH / BM), NTHREADS, SMEM_TOTAL>>>(
        h1, wt_w2, b2, w3, pb);
    // out = relu(sum pb + b3)
    combine_out<<<(BATCH * ACT + 255) / 256, 256>>>(pb, b3, out);
}

// round 14
// speedup vs baseline: 1.2840x; 1.0443x over previous
#include <cuda_runtime.h>
#include <cuda_fp16.h>
#include <cstdint>

// ===================== problem dims =====================
static constexpr int BATCH    = 16384;
static constexpr int DGPE_IN  = 1536;
static constexpr int DGPE_OUT = 1536;
static constexpr int DGPI_IN  = 3072;
static constexpr int DGPI_OUT = 1536;
static constexpr int U3       = 512;
static constexpr int ACT      = 6;

// ===================== device scratch (no cudaMalloc allowed) =====================
__device__ __half g_xh     [(size_t)BATCH * DGPE_IN];        // x as fp16
__device__ __half g_wt_gpiB[DGPI_OUT * DGPE_OUT];            // [j][k] masked Wg^T (gpi cols 1536:3072)
__device__ __half g_wm_gpe [DGPE_IN * DGPE_OUT];             // [i][k] masked gpe W (non-transposed)
__device__ float  g_wx32   [DGPE_IN * DGPI_OUT];             // [i][j] masked Wx (fp32, exact)
__device__ float  g_we_p0  [DGPE_IN * DGPI_OUT];             // W_eff K-split partials (fp32)
__device__ float  g_we_p1  [DGPE_IN * DGPI_OUT];
__device__ __half g_weffs  [(size_t)DGPE_IN * 3 * DGPI_OUT]; // [i][ hi | hi | lo ]
__device__ __half g_w1s    [U3 * 2 * DGPI_OUT];              // [n][ hi | lo ]
__device__ float  g_wf_q   [(size_t)3 * U3 * DGPE_IN];       // W_full 3-way partials (fp32)
__device__ __half g_wfull_h[U3 * DGPE_IN];                   // [n][i] fp16 final
__device__ float  g_bias_eff[DGPI_OUT];
__device__ float  g_bias_full[U3];
__device__ __half g_wt_w2  [U3 * U3];
__device__ __half g_h1[(size_t)BATCH * U3];
__device__ float  g_pb[(size_t)4 * BATCH * 8];               // fused-out partials

// ===================== helpers =====================
__device__ __forceinline__ uint32_t smem_u32(const void* p) {
    return (uint32_t)__cvta_generic_to_shared(p);
}
#define CP_ASYNC16(dst, src) \
    asm volatile("cp.async.cg.shared.global [%0], [%1], 16;\n" :: "r"(dst), "l"(src))
#define CP_ASYNC_COMMIT() asm volatile("cp.async.commit_group;\n" ::: "memory")
#define CP_ASYNC_WAIT(n)  asm volatile("cp.async.wait_group %0;\n" :: "n"(n) : "memory")

__device__ __forceinline__ uint32_t swz64(uint32_t byte_off) {
    return byte_off ^ ((byte_off >> 3) & 0x30);
}

__device__ __forceinline__ void ldmatrix_x4(uint32_t r[4], uint32_t addr) {
    asm volatile("ldmatrix.sync.aligned.m8n8.x4.shared.b16 {%0,%1,%2,%3}, [%4];"
                 : "=r"(r[0]), "=r"(r[1]), "=r"(r[2]), "=r"(r[3]) : "r"(addr));
}

__device__ __forceinline__ void mma_f16(float c[4], const uint32_t a[4],
                                        uint32_t b0, uint32_t b1) {
    asm volatile(
        "mma.sync.aligned.m16n8k16.row.col.f32.f16.f16.f32 "
        "{%0,%1,%2,%3}, {%4,%5,%6,%7}, {%8,%9}, {%0,%1,%2,%3};"
        : "+f"(c[0]), "+f"(c[1]), "+f"(c[2]), "+f"(c[3])
        : "r"(a[0]), "r"(a[1]), "r"(a[2]), "r"(a[3]), "r"(b0), "r"(b1));
}

// ===================== GEMM config =====================
static constexpr int BM = 128, BN = 128, BK = 32, STAGES = 4, NTHREADS = 256;
static constexpr int A_STAGE_BYTES = BM * BK * 2;
static constexpr int B_STAGE_BYTES = BN * BK * 2;
static constexpr int STAGE_BYTES   = A_STAGE_BYTES + B_STAGE_BYTES;
static constexpr int SMEM_BIAS     = 0;       // 128 floats
static constexpr int SMEM_W3      = 512;      // 128*6 floats (fused kernel only)
static constexpr int SMEM_TILES    = 4096;
static constexpr int SMEM_TOTAL    = SMEM_TILES + STAGES * STAGE_BYTES; // 69632

// D[m,n] = sum_k A[m,k] * BT[n*ldb + k] (+ bias[n]) (optional ReLU)
// out_mode: 0 = fp16 D (ld N), 1 = fp32 D (ld N).
// A K-split: k < ksplit -> A0 (lda0) else A1 (lda1, k-ksplit). ksplit % BK == 0.
__global__ void __launch_bounds__(NTHREADS, 2)
gemm_f16(const __half* __restrict__ A0, const __half* __restrict__ A1,
         int ksplit, int lda0, int lda1,
         const __half* __restrict__ BT, int ldb, const float* __restrict__ bias,
         void* __restrict__ D, int out_mode, int N, int K, int do_relu)
{
    extern __shared__ char smem[];
    float* sb_bias = (float*)(smem + SMEM_BIAS);
    const uint32_t stile = smem_u32(smem) + SMEM_TILES;
    const int tid  = threadIdx.x;
    const int wid  = tid >> 5;
    const int lane = tid & 31;
    const int g    = lane >> 2;
    const int t    = lane & 3;
    const int m0 = blockIdx.y * BM;
    const int n0 = blockIdx.x * BN;
    const int warp_m = (wid >> 2) * 64;
    const int warp_n = (wid & 3) * 32;

    if (tid < BN) sb_bias[tid] = bias ? bias[n0 + tid] : 0.f;

    const int KB = K / BK;

    auto load_stage = [&](int kb) {
        const int s = kb & (STAGES - 1);
        const int k0 = kb * BK;
        const uint32_t a_base = stile + s * STAGE_BYTES;
        const uint32_t b_base = a_base + A_STAGE_BYTES;
        #pragma unroll
        for (int j = 0; j < 2; j++) {
            int idx = tid + j * NTHREADS;
            int row = idx >> 2;
            int c   = idx & 3;
            int kg  = k0 + (c << 3);
            const __half* src = (kg < ksplit)
                ? (A0 + (size_t)(m0 + row) * lda0 + kg)
                : (A1 + (size_t)(m0 + row) * lda1 + (kg - ksplit));
            uint32_t dst = a_base + swz64((uint32_t)(row * 64 + (c << 4)));
            CP_ASYNC16(dst, src);
        }
        #pragma unroll
        for (int j = 0; j < 2; j++) {
            int idx = tid + j * NTHREADS;
            int row = idx >> 2;
            int c   = idx & 3;
            const __half* src = BT + (size_t)(n0 + row) * ldb + k0 + (c << 3);
            uint32_t dst = b_base + swz64((uint32_t)(row * 64 + (c << 4)));
            CP_ASYNC16(dst, src);
        }
        CP_ASYNC_COMMIT();
    };

    float acc[4][4][4];
    #pragma unroll
    for (int mt = 0; mt < 4; mt++)
        #pragma unroll
        for (int nt = 0; nt < 4; nt++)
            #pragma unroll
            for (int r = 0; r < 4; r++) acc[mt][nt][r] = 0.f;

    const int lm_row = (lane & 8) + (lane & 7);
    const int lm_k   = (lane & 16) >> 1;

    load_stage(0); load_stage(1); load_stage(2);

    for (int kb = 0; kb < KB; kb++) {
        if (kb < KB - 3) { CP_ASYNC_WAIT(2); } else { CP_ASYNC_WAIT(0); }
        __syncthreads();
        if (kb + 3 < KB) load_stage(kb + 3);

        const int s = kb & (STAGES - 1);
        const uint32_t As = stile + s * STAGE_BYTES;
        const uint32_t Bs = As + A_STAGE_BYTES;

        #pragma unroll
        for (int ks = 0; ks < 2; ks++) {
            const int kk = ks * 16;
            uint32_t am[4][4], bm[2][4];
            #pragma unroll
            for (int mt = 0; mt < 4; mt++) {
                int row = warp_m + mt * 16 + lm_row;
                ldmatrix_x4(am[mt], As + swz64((uint32_t)(row * 64 + (kk + lm_k) * 2)));
            }
            #pragma unroll
            for (int pr = 0; pr < 2; pr++) {
                int row = warp_n + pr * 16 + lm_row;
                ldmatrix_x4(bm[pr], Bs + swz64((uint32_t)(row * 64 + (kk + lm_k) * 2)));
            }
            #pragma unroll
            for (int mt = 0; mt < 4; mt++)
                #pragma unroll
                for (int nt = 0; nt < 4; nt++)
                    mma_f16(acc[mt][nt], am[mt], bm[nt >> 1][nt & 1], bm[nt >> 1][(nt & 1) + 2]);
        }
    }

    // epilogue
    #pragma unroll
    for (int mt = 0; mt < 4; mt++) {
        const int row = m0 + warp_m + mt * 16 + g;
        #pragma unroll
        for (int nt = 0; nt < 4; nt++) {
            const int cb = warp_n + nt * 8 + t * 2;
            const int col = n0 + cb;
            float b0 = sb_bias[cb], b1 = sb_bias[cb + 1];
            float2 v0 = make_float2(acc[mt][nt][0] + b0, acc[mt][nt][1] + b1);
            float2 v1 = make_float2(acc[mt][nt][2] + b0, acc[mt][nt][3] + b1);
            if (do_relu) {
                v0.x = fmaxf(v0.x, 0.f); v0.y = fmaxf(v0.y, 0.f);
                v1.x = fmaxf(v1.x, 0.f); v1.y = fmaxf(v1.y, 0.f);
            }
            if (out_mode == 0) {
                __half* Dh = (__half*)D;
                *reinterpret_cast<__half2*>(Dh + (size_t)row * N + col)       = __floats2half2_rn(v0.x, v0.y);
                *reinterpret_cast<__half2*>(Dh + (size_t)(row + 8) * N + col) = __floats2half2_rn(v1.x, v1.y);
            } else {
                float* Df = (float*)D;
                *reinterpret_cast<float2*>(Df + (size_t)row * N + col)       = v0;
                *reinterpret_cast<float2*>(Df + (size_t)(row + 8) * N + col) = v1;
            }
        }
    }
}

// ============ fused h2+final: pb[bx][m][0:6] = relu(h1@w2+b2)[m, n0:n0+128] @ w3[n0:n0+128] ====
__global__ void __launch_bounds__(NTHREADS, 2)
gemm_h2_fused(const __half* __restrict__ A, const __half* __restrict__ BT,
              const float* __restrict__ bias, const float* __restrict__ w3,
              float* __restrict__ pb)
{
    extern __shared__ char smem[];
    float* sb_bias = (float*)(smem + SMEM_BIAS);
    float* w3s     = (float*)(smem + SMEM_W3);     // [128][6]
    const uint32_t stile = smem_u32(smem) + SMEM_TILES;
    const int tid  = threadIdx.x;
    const int wid  = tid >> 5;
    const int lane = tid & 31;
    const int g    = lane >> 2;
    const int t    = lane & 3;
    const int m0 = blockIdx.y * BM;
    const int n0 = blockIdx.x * BN;
    const int warp_m = (wid >> 2) * 64;
    const int warp_n = (wid & 3) * 32;
    const int K = U3, ldab = U3;

    if (tid < BN) sb_bias[tid] = bias[n0 + tid];
    for (int i = tid; i < BN * ACT; i += NTHREADS)
        w3s[i] = w3[(size_t)(n0 + i / ACT) * ACT + (i % ACT)];

    const int KB = K / BK;   // 16

    auto load_stage = [&](int kb) {
        const int s = kb & (STAGES - 1);
        const int k0 = kb * BK;
        const uint32_t a_base = stile + s * STAGE_BYTES;
        const uint32_t b_base = a_base + A_STAGE_BYTES;
        #pragma unroll
        for (int j = 0; j < 2; j++) {
            int idx = tid + j * NTHREADS;
            int row = idx >> 2;
            int c   = idx & 3;
            const __half* src = A + (size_t)(m0 + row) * ldab + k0 + (c << 3);
            uint32_t dst = a_base + swz64((uint32_t)(row * 64 + (c << 4)));
            CP_ASYNC16(dst, src);
        }
        #pragma unroll
        for (int j = 0; j < 2; j++) {
            int idx = tid + j * NTHREADS;
            int row = idx >> 2;
            int c   = idx & 3;
            const __half* src = BT + (size_t)(n0 + row) * ldab + k0 + (c << 3);
            uint32_t dst = b_base + swz64((uint32_t)(row * 64 + (c << 4)));
            CP_ASYNC16(dst, src);
        }
        CP_ASYNC_COMMIT();
    };

    float acc[4][4][4];
    #pragma unroll
    for (int mt = 0; mt < 4; mt++)
        #pragma unroll
        for (int nt = 0; nt < 4; nt++)
            #pragma unroll
            for (int r = 0; r < 4; r++) acc[mt][nt][r] = 0.f;

    const int lm_row = (lane & 8) + (lane & 7);
    const int lm_k   = (lane & 16) >> 1;

    load_stage(0); load_stage(1); load_stage(2);

    for (int kb = 0; kb < KB; kb++) {
        if (kb < KB - 3) { CP_ASYNC_WAIT(2); } else { CP_ASYNC_WAIT(0); }
        __syncthreads();
        if (kb + 3 < KB) load_stage(kb + 3);

        const int s = kb & (STAGES - 1);
        const uint32_t As = stile + s * STAGE_BYTES;
        const uint32_t Bs = As + A_STAGE_BYTES;

        #pragma unroll
        for (int ks = 0; ks < 2; ks++) {
            const int kk = ks * 16;
            uint32_t am[4][4], bm[2][4];
            #pragma unroll
            for (int mt = 0; mt < 4; mt++) {
                int row = warp_m + mt * 16 + lm_row;
                ldmatrix_x4(am[mt], As + swz64((uint32_t)(row * 64 + (kk + lm_k) * 2)));
            }
            #pragma unroll
            for (int pr = 0; pr < 2; pr++) {
                int row = warp_n + pr * 16 + lm_row;
                ldmatrix_x4(bm[pr], Bs + swz64((uint32_t)(row * 64 + (kk + lm_k) * 2)));
            }
            #pragma unroll
            for (int mt = 0; mt < 4; mt++)
                #pragma unroll
                for (int nt = 0; nt < 4; nt++)
                    mma_f16(acc[mt][nt], am[mt], bm[nt >> 1][nt & 1], bm[nt >> 1][(nt & 1) + 2]);
        }
    }

    // fused epilogue: v = relu(acc + bias); P[row][n] += v * w3s  (deterministic)
    float* Pw = (float*)(smem + SMEM_TILES);   // [4][128][6], reuses tile region
    __syncthreads();
    #pragma unroll
    for (int mt = 0; mt < 4; mt++) {
        float s0[ACT] = {0,0,0,0,0,0}, s1[ACT] = {0,0,0,0,0,0};
        #pragma unroll
        for (int nt = 0; nt < 4; nt++) {
            const int cb = warp_n + nt * 8 + t * 2;
            float b0 = sb_bias[cb], b1v = sb_bias[cb + 1];
            float v00 = fmaxf(acc[mt][nt][0] + b0,  0.f);
            float v01 = fmaxf(acc[mt][nt][1] + b1v, 0.f);
            float v10 = fmaxf(acc[mt][nt][2] + b0,  0.f);
            float v11 = fmaxf(acc[mt][nt][3] + b1v, 0.f);
            #pragma unroll
            for (int n = 0; n < ACT; n++) {
                float w0 = w3s[cb * ACT + n], w1v = w3s[(cb + 1) * ACT + n];
                s0[n] += v00 * w0 + v01 * w1v;
                s1[n] += v10 * w0 + v11 * w1v;
            }
        }
        #pragma unroll
        for (int n = 0; n < ACT; n++) {
            s0[n] += __shfl_xor_sync(0xffffffffu, s0[n], 1);
            s0[n] += __shfl_xor_sync(0xffffffffu, s0[n], 2);
            s1[n] += __shfl_xor_sync(0xffffffffu, s1[n], 1);
            s1[n] += __shfl_xor_sync(0xffffffffu, s1[n], 2);
        }
        if (t == 0) {
            const int wn = wid & 3;
            const int rl = warp_m + mt * 16 + g;
            #pragma unroll
            for (int n = 0; n < ACT; n++) {
                Pw[(wn * 128 + rl) * ACT + n]     = s0[n];
                Pw[(wn * 128 + rl + 8) * ACT + n] = s1[n];
            }
        }
    }
    __syncthreads();
    if (tid < 128) {
        #pragma unroll
        for (int n = 0; n < ACT; n++) {
            float s = Pw[(0 * 128 + tid) * ACT + n] + Pw[(1 * 128 + tid) * ACT + n]
                    + Pw[(2 * 128 + tid) * ACT + n] + Pw[(3 * 128 + tid) * ACT + n];
            pb[((size_t)blockIdx.x * BATCH + m0 + tid) * 8 + n] = s;
        }
    }
}

// out[m][n] = relu(b3[n] + sum_bx pb[bx][m][n])
__global__ void combine_out(const float* __restrict__ pb, const float* __restrict__ b3,
                            float* __restrict__ out)
{
    int idx = blockIdx.x * blockDim.x + threadIdx.x;
    if (idx >= BATCH * ACT) return;
    int m = idx / ACT, n = idx % ACT;
    float s = b3[n];
    #pragma unroll
    for (int bx = 0; bx < 4; bx++)
        s += pb[((size_t)bx * BATCH + m) * 8 + n];
    out[(size_t)m * ACT + n] = fmaxf(s, 0.f);
}

// ===================== weight prep kernels =====================
// wt[n][k] = f16(w[k][n] * mask[n*mask_ld + mask_koff + k])
__global__ void transpose_mask(const float* __restrict__ w, const float* __restrict__ mask,
                               __half* __restrict__ wt, int K, int N, int mask_ld, int mask_koff)
{
    __shared__ float tile[32][33];
    const int k0 = blockIdx.x * 32, n0 = blockIdx.y * 32;
    const int tx = threadIdx.x, ty = threadIdx.y;
    #pragma unroll
    for (int j = 0; j < 32; j += 8)
        tile[ty + j][tx] = w[(size_t)(k0 + ty + j) * N + n0 + tx];
    __syncthreads();
    #pragma unroll
    for (int j = 0; j < 32; j += 8) {
        const int n = n0 + ty + j, k = k0 + tx;
        float v = tile[tx][ty + j];
        if (mask) v *= mask[(size_t)n * mask_ld + mask_koff + k];
        wt[(size_t)n * K + k] = __float2half_rn(v);
    }
}

__global__ void transpose_split_w1(const float* __restrict__ w, __half* __restrict__ w1s,
                                   int K, int N)
{
    __shared__ float tile[32][33];
    const int k0 = blockIdx.x * 32, n0 = blockIdx.y * 32;
    const int tx = threadIdx.x, ty = threadIdx.y;
    #pragma unroll
    for (int j = 0; j < 32; j += 8)
        tile[ty + j][tx] = w[(size_t)(k0 + ty + j) * N + n0 + tx];
    __syncthreads();
    #pragma unroll
    for (int j = 0; j < 32; j += 8) {
        const int n = n0 + ty + j, k = k0 + tx;
        float v = tile[tx][ty + j];
        __half hi = __float2half_rn(v);
        __half lo = __float2half_rn(v - __half2float(hi));
        w1s[(size_t)n * (2 * K) + k]     = hi;
        w1s[(size_t)n * (2 * K) + K + k] = lo;
    }
}

__global__ void mask_apply_nt(const float* __restrict__ w, const float* __restrict__ mask,
                              int mstride, __half* __restrict__ out, int J)
{
    __shared__ float mt[32][33];
    const int i0 = blockIdx.y * 32, j0 = blockIdx.x * 32;
    const int tx = threadIdx.x, ty = threadIdx.y;
    #pragma unroll
    for (int jj = 0; jj < 32; jj += 8)
        mt[ty + jj][tx] = mask[(size_t)(j0 + ty + jj) * mstride + i0 + tx];
    __syncthreads();
    #pragma unroll
    for (int jj = 0; jj < 32; jj += 8) {
        const int i = i0 + ty + jj, j = j0 + tx;
        out[(size_t)i * J + j] = __float2half_rn(w[(size_t)i * J + j] * mt[tx][ty + jj]);
    }
}

__global__ void mask_apply_nt_f32(const float* __restrict__ w, const float* __restrict__ mask,
                                  int mstride, float* __restrict__ out, int J)
{
    __shared__ float mt[32][33];
    const int i0 = blockIdx.y * 32, j0 = blockIdx.x * 32;
    const int tx = threadIdx.x, ty = threadIdx.y;
    #pragma unroll
    for (int jj = 0; jj < 32; jj += 8)
        mt[ty + jj][tx] = mask[(size_t)(j0 + ty + jj) * mstride + i0 + tx];
    __syncthreads();
    #pragma unroll
    for (int jj = 0; jj < 32; jj += 8) {
        const int i = i0 + ty + jj, j = j0 + tx;
        out[(size_t)i * J + j] = w[(size_t)i * J + j] * mt[tx][ty + jj];
    }
}

// weffs[i][ hi | hi | lo ] from p0+p1+wx (fp32 sum, deterministic).
// grid: (J/(128*4), DGPE_IN), block 128. J = DGPI_OUT.
__global__ void reduce_split3(const float* __restrict__ p0, const float* __restrict__ p1,
                              const float* __restrict__ wx, __half* __restrict__ dst, int J)
{
    const int i = blockIdx.y;
    const int j = (blockIdx.x * blockDim.x + threadIdx.x) * 4;
    const size_t src = (size_t)i * J + j;
    float4 a = *reinterpret_cast<const float4*>(p0 + src);
    float4 b = *reinterpret_cast<const float4*>(p1 + src);
    float4 c = *reinterpret_cast<const float4*>(wx + src);
    float v0 = a.x + b.x + c.x, v1 = a.y + b.y + c.y;
    float v2 = a.z + b.z + c.z, v3 = a.w + b.w + c.w;
    __half2 h01 = __floats2half2_rn(v0, v1);
    __half2 h23 = __floats2half2_rn(v2, v3);
    __half2 l01 = __floats2half2_rn(v0 - __half2float(h01.x), v1 - __half2float(h01.y));
    __half2 l23 = __floats2half2_rn(v2 - __half2float(h23.x), v3 - __half2float(h23.y));
    const size_t base = (size_t)i * (3 * J);
    *reinterpret_cast<__half2*>(dst + base + j)             = h01;
    *reinterpret_cast<__half2*>(dst + base + j + 2)         = h23;
    *reinterpret_cast<__half2*>(dst + base + J + j)         = h01;
    *reinterpret_cast<__half2*>(dst + base + J + j + 2)     = h23;
    *reinterpret_cast<__half2*>(dst + base + 2 * J + j)     = l01;
    *reinterpret_cast<__half2*>(dst + base + 2 * J + j + 2) = l23;
}

// wfull_h = f16(sum of 3 partials), vectorized; stride = U3*DGPE_IN per partial
__global__ void reduce3q_f16(const float* __restrict__ q, __half* __restrict__ out)
{
    const size_t STRIDE = (size_t)U3 * DGPE_IN;
    int i = (blockIdx.x * blockDim.x + threadIdx.x) * 4;
    float4 s = *reinterpret_cast<const float4*>(q + i);
    #pragma unroll
    for (int z = 1; z < 3; z++) {
        float4 a = *reinterpret_cast<const float4*>(q + z * STRIDE + i);
        s.x += a.x; s.y += a.y; s.z += a.z; s.w += a.w;
    }
    *reinterpret_cast<__half2*>(out + i)     = __floats2half2_rn(s.x, s.y);
    *reinterpret_cast<__half2*>(out + i + 2) = __floats2half2_rn(s.z, s.w);
}

__global__ void bias_eff_kernel(const float* __restrict__ gpi_w, const float* __restrict__ gpi_mask,
                                const float* __restrict__ gpe_b,
                                const float* __restrict__ gpi_b, float* __restrict__ be)
{
    const int n = blockIdx.x * 8 + (threadIdx.x >> 5);
    const int lane = threadIdx.x & 31;
    const float* mrow = gpi_mask + (size_t)n * DGPI_IN + DGPE_IN;
    float s0 = 0.f, s1 = 0.f;
    for (int j = lane; j < DGPE_OUT; j += 64) {
        s0 += gpi_w[(size_t)(DGPE_IN + j) * DGPI_OUT + n] * mrow[j] * gpe_b[j];
        int j2 = j + 32;
        s1 += gpi_w[(size_t)(DGPE_IN + j2) * DGPI_OUT + n] * mrow[j2] * gpe_b[j2];
    }
    float s = s0 + s1;
    #pragma unroll
    for (int off = 16; off; off >>= 1) s += __shfl_xor_sync(0xffffffffu, s, off);
    if (lane == 0) be[n] = gpi_b[n] + s;
}

__global__ void bias_full_kernel(const float* __restrict__ be, const float* __restrict__ w1,
                                 const float* __restrict__ b1, float* __restrict__ bf)
{
    const int n = blockIdx.x * 8 + (threadIdx.x >> 5);
    const int lane = threadIdx.x & 31;
    float s0 = 0.f, s1 = 0.f;
    for (int j = lane; j < DGPI_OUT; j += 64) {
        s0 += be[j] * w1[(size_t)j * U3 + n];
        s1 += be[j + 32] * w1[(size_t)(j + 32) * U3 + n];
    }
    float s = s0 + s1;
    #pragma unroll
    for (int off = 16; off; off >>= 1) s += __shfl_xor_sync(0xffffffffu, s, off);
    if (lane == 0) bf[n] = b1[n] + s;
}

__global__ void convert_f2h(const float* __restrict__ src, __half* __restrict__ dst, int n)
{
    int i = (blockIdx.x * blockDim.x + threadIdx.x) * 4;
    if (i < n) {
        float4 v = *reinterpret_cast<const float4*>(src + i);
        *reinterpret_cast<__half2*>(dst + i)     = __floats2half2_rn(v.x, v.y);
        *reinterpret_cast<__half2*>(dst + i + 2) = __floats2half2_rn(v.z, v.w);
    }
}

// ===================== launch =====================
extern "C" void kernel_launch(void* const* d_in, const int* in_sizes, int n_in,
                              void* d_out, int out_size)
{
    const float* x        = (const float*)d_in[0];
    const float* gpe_mask = (const float*)d_in[1];
    const float* gpe_w    = (const float*)d_in[2];
    const float* gpe_b    = (const float*)d_in[3];
    const float* gpi_mask = (const float*)d_in[4];
    const float* gpi_w    = (const float*)d_in[5];
    const float* gpi_b    = (const float*)d_in[6];
    const float* w1       = (const float*)d_in[7];
    const float* b1       = (const float*)d_in[8];
    const float* w2       = (const float*)d_in[9];
    const float* b2       = (const float*)d_in[10];
    const float* w3       = (const float*)d_in[11];
    const float* b3       = (const float*)d_in[12];
    float* out = (float*)d_out;

    __half *xh, *wt_gpiB, *wm_gpe, *weffs, *w1s, *wfull_h, *wt_w2, *h1;
    float *wx32, *we_p0, *we_p1, *wf_q, *bias_eff, *bias_full, *pb;
    cudaGetSymbolAddress((void**)&xh,        g_xh);
    cudaGetSymbolAddress((void**)&wt_gpiB,   g_wt_gpiB);
    cudaGetSymbolAddress((void**)&wm_gpe,    g_wm_gpe);
    cudaGetSymbolAddress((void**)&wx32,      g_wx32);
    cudaGetSymbolAddress((void**)&we_p0,     g_we_p0);
    cudaGetSymbolAddress((void**)&we_p1,     g_we_p1);
    cudaGetSymbolAddress((void**)&weffs,     g_weffs);
    cudaGetSymbolAddress((void**)&w1s,       g_w1s);
    cudaGetSymbolAddress((void**)&wf_q,      g_wf_q);
    cudaGetSymbolAddress((void**)&wfull_h,   g_wfull_h);
    cudaGetSymbolAddress((void**)&bias_eff,  g_bias_eff);
    cudaGetSymbolAddress((void**)&bias_full, g_bias_full);
    cudaGetSymbolAddress((void**)&wt_w2,     g_wt_w2);
    cudaGetSymbolAddress((void**)&h1,        g_h1);
    cudaGetSymbolAddress((void**)&pb,        g_pb);

    cudaFuncSetAttribute(gemm_f16,      cudaFuncAttributeMaxDynamicSharedMemorySize, SMEM_TOTAL);
    cudaFuncSetAttribute(gemm_h2_fused, cudaFuncAttributeMaxDynamicSharedMemorySize, SMEM_TOTAL);

    // 3 streams max — proven-safe resource footprint (6 streams tripped the
    // device-memory guard by growing the driver pool).
    static cudaStream_t sA = nullptr, sB = nullptr, sC = nullptr;
    static cudaEvent_t evRoot, evGpi, evMsk, evWx, evW1s, evW2, evWeP1, evWeffs,
                       evQ1, evQ2, evWfull, evBias;
    if (sA == nullptr) {
        cudaStreamCreateWithFlags(&sA, cudaStreamNonBlocking);
        cudaStreamCreateWithFlags(&sB, cudaStreamNonBlocking);
        cudaStreamCreateWithFlags(&sC, cudaStreamNonBlocking);
        cudaEventCreateWithFlags(&evRoot,  cudaEventDisableTiming);
        cudaEventCreateWithFlags(&evGpi,   cudaEventDisableTiming);
        cudaEventCreateWithFlags(&evMsk,   cudaEventDisableTiming);
        cudaEventCreateWithFlags(&evWx,    cudaEventDisableTiming);
        cudaEventCreateWithFlags(&evW1s,   cudaEventDisableTiming);
        cudaEventCreateWithFlags(&evW2,    cudaEventDisableTiming);
        cudaEventCreateWithFlags(&evWeP1,  cudaEventDisableTiming);
        cudaEventCreateWithFlags(&evWeffs, cudaEventDisableTiming);
        cudaEventCreateWithFlags(&evQ1,    cudaEventDisableTiming);
        cudaEventCreateWithFlags(&evQ2,    cudaEventDisableTiming);
        cudaEventCreateWithFlags(&evWfull, cudaEventDisableTiming);
        cudaEventCreateWithFlags(&evBias,  cudaEventDisableTiming);
    }

    const dim3 tb(32, 8);
    const int nx = BATCH * DGPE_IN;
    const int KH = DGPE_OUT / 2;   // 768 K-half for W_eff split
    const size_t QSTRIDE = (size_t)U3 * DGPE_IN;

    // ---- fork ----
    cudaEventRecord(evRoot, 0);
    cudaStreamWaitEvent(sA, evRoot, 0);
    cudaStreamWaitEvent(sB, evRoot, 0);
    cudaStreamWaitEvent(sC, evRoot, 0);

    // L: x conversion (big, independent), then off-path bias chain
    convert_f2h<<<(nx / 4 + 255) / 256, 256>>>(x, xh, nx);
    bias_eff_kernel<<<DGPI_OUT / 8, 256>>>(gpi_w, gpi_mask, gpe_b, gpi_b, bias_eff);
    bias_full_kernel<<<U3 / 8, 256>>>(bias_eff, w1, b1, bias_full);
    cudaEventRecord(evBias, 0);

    // sA: HALF gpi transpose (Wg block)
    transpose_mask<<<dim3(DGPE_OUT / 32, DGPI_OUT / 32), tb, 0, sA>>>(
        gpi_w + (size_t)DGPE_IN * DGPI_OUT, gpi_mask, wt_gpiB,
        DGPE_OUT, DGPI_OUT, DGPI_IN, DGPE_IN);
    cudaEventRecord(evGpi, sA);

    // sB: gpe mask
    mask_apply_nt<<<dim3(DGPE_OUT / 32, DGPE_IN / 32), tb, 0, sB>>>(gpe_w, gpe_mask, DGPE_IN, wm_gpe, DGPE_OUT);
    cudaEventRecord(evMsk, sB);

    // sC: wx32, w1 split, w2 transpose
    mask_apply_nt_f32<<<dim3(DGPI_OUT / 32, DGPE_IN / 32), tb, 0, sC>>>(gpi_w, gpi_mask, DGPI_IN, wx32, DGPI_OUT);
    cudaEventRecord(evWx, sC);
    transpose_split_w1<<<dim3(DGPI_OUT / 32, U3 / 32), tb, 0, sC>>>(w1, w1s, DGPI_OUT, U3);
    cudaEventRecord(evW1s, sC);
    transpose_mask<<<dim3(U3 / 32, U3 / 32), tb, 0, sC>>>(w2, nullptr, wt_w2, U3, U3, U3, 0);
    cudaEventRecord(evW2, sC);

    // W_eff split-K: two concurrent K=768 GEMMs -> fp32 partials
    cudaStreamWaitEvent(sB, evGpi, 0);
    gemm_f16<<<dim3(DGPI_OUT / BN, DGPE_IN / BM), NTHREADS, SMEM_TOTAL, sB>>>(
        wm_gpe, wm_gpe, KH, DGPE_OUT, DGPE_OUT,
        wt_gpiB, DGPE_OUT, nullptr, we_p0, 1, DGPI_OUT, KH, 0);
    cudaStreamWaitEvent(sA, evMsk, 0);
    gemm_f16<<<dim3(DGPI_OUT / BN, DGPE_IN / BM), NTHREADS, SMEM_TOTAL, sA>>>(
        wm_gpe + KH, wm_gpe + KH, KH, DGPE_OUT, DGPE_OUT,
        wt_gpiB + KH, DGPE_OUT, nullptr, we_p1, 1, DGPI_OUT, KH, 0);
    cudaEventRecord(evWeP1, sA);

    // reduce + hi/lo 3-segment split (adds wx32) on sB
    cudaStreamWaitEvent(sB, evWeP1, 0);
    cudaStreamWaitEvent(sB, evWx, 0);
    reduce_split3<<<dim3(DGPI_OUT / (128 * 4), DGPE_IN), 128, 0, sB>>>(
        we_p0, we_p1, wx32, weffs, DGPI_OUT);
    cudaEventRecord(evWeffs, sB);

    // W_full: 3 concurrent K=1536 GEMMs (hi@hi on sB, lo@hi on sA, hi@lo on sC)
    cudaStreamWaitEvent(sB, evW1s, 0);
    gemm_f16<<<dim3(DGPE_IN / BN, U3 / BM), NTHREADS, SMEM_TOTAL, sB>>>(
        w1s, w1s, DGPI_OUT, 2 * DGPI_OUT, 2 * DGPI_OUT,
        weffs, 3 * DGPI_OUT, nullptr, wf_q, 1, DGPE_IN, DGPI_OUT, 0);
    cudaStreamWaitEvent(sA, evWeffs, 0);
    cudaStreamWaitEvent(sA, evW1s, 0);
    gemm_f16<<<dim3(DGPE_IN / BN, U3 / BM), NTHREADS, SMEM_TOTAL, sA>>>(
        w1s + DGPI_OUT, w1s + DGPI_OUT, DGPI_OUT, 2 * DGPI_OUT, 2 * DGPI_OUT,
        weffs + DGPI_OUT, 3 * DGPI_OUT, nullptr, wf_q + QSTRIDE, 1, DGPE_IN, DGPI_OUT, 0);
    cudaEventRecord(evQ1, sA);
    cudaStreamWaitEvent(sC, evWeffs, 0);
    gemm_f16<<<dim3(DGPE_IN / BN, U3 / BM), NTHREADS, SMEM_TOTAL, sC>>>(
        w1s, w1s, DGPI_OUT, 2 * DGPI_OUT, 2 * DGPI_OUT,
        weffs + 2 * DGPI_OUT, 3 * DGPI_OUT, nullptr, wf_q + 2 * QSTRIDE, 1, DGPE_IN, DGPI_OUT, 0);
    cudaEventRecord(evQ2, sC);

    // reduce 3 partials -> fp16 W_full on sB
    cudaStreamWaitEvent(sB, evQ1, 0);
    cudaStreamWaitEvent(sB, evQ2, 0);
    reduce3q_f16<<<(int)(QSTRIDE / 4 / 256), 256, 0, sB>>>(wf_q, wfull_h);
    cudaEventRecord(evWfull, sB);

    // ---- join ----
    cudaStreamWaitEvent(0, evWfull, 0);
    cudaStreamWaitEvent(0, evW2, 0);

    // h1 = relu(x @ W_full + bias_full)   (25.8 GF)
    gemm_f16<<<dim3(U3 / BN, BATCH / BM), NTHREADS, SMEM_TOTAL>>>(
        xh, xh, DGPE_IN, DGPE_IN, DGPE_IN,
        wfull_h, DGPE_IN, bias_full, h1, 0, U3, DGPE_IN, 1);
    // fused: pb = relu(h1 @ w2 + b2) @ w3  (per n-block partials)
    gemm_h2_fused<<<dim3(U3 / BN, BATCH / BM), NTHREADS, SMEM_TOTAL>>>(
        h1, wt_w2, b2, w3, pb);
    // out = relu(sum pb + b3)
    combine_out<<<(BATCH * ACT + 255) / 256, 256>>>(pb, b3, out);
}

// round 15
// speedup vs baseline: 1.4236x; 1.1087x over previous
#include <cuda_runtime.h>
#include <cuda_fp16.h>
#include <cstdint>

// ===================== problem dims =====================
static constexpr int BATCH    = 16384;
static constexpr int DGPE_IN  = 1536;
static constexpr int DGPE_OUT = 1536;
static constexpr int DGPI_IN  = 3072;
static constexpr int DGPI_OUT = 1536;
static constexpr int U3       = 512;
static constexpr int ACT      = 6;

// ===================== device scratch (no cudaMalloc allowed) =====================
__device__ __half g_xh     [(size_t)BATCH * DGPE_IN];        // x as fp16
__device__ __half g_wt_gpiB[DGPI_OUT * DGPE_OUT];            // [j][k] masked Wg^T (gpi cols 1536:3072)
__device__ __half g_wm_gpe [DGPE_IN * DGPE_OUT];             // [i][k] masked gpe W (non-transposed)
__device__ float  g_wx32   [DGPE_IN * DGPI_OUT];             // [i][j] masked Wx (fp32, exact)
__device__ float  g_we_p   [(size_t)2 * DGPE_IN * DGPI_OUT]; // W_eff K-split partials (contiguous)
__device__ __half g_weffs  [(size_t)DGPE_IN * 3 * DGPI_OUT]; // [i][ hi | hi | lo ]
__device__ __half g_w1s    [U3 * 2 * DGPI_OUT];              // [n][ hi | lo ]
__device__ float  g_wf_q   [(size_t)3 * U3 * DGPE_IN];       // W_full 3-way partials (fp32)
__device__ __half g_wfull_h[U3 * DGPE_IN];                   // [n][i] fp16 final
__device__ float  g_bias_eff[DGPI_OUT];
__device__ float  g_bias_full[U3];
__device__ __half g_wt_w2  [U3 * U3];
__device__ __half g_h1[(size_t)BATCH * U3];
__device__ float  g_pb[(size_t)4 * BATCH * 8];               // fused-out partials

// ===================== helpers =====================
__device__ __forceinline__ uint32_t smem_u32(const void* p) {
    return (uint32_t)__cvta_generic_to_shared(p);
}
#define CP_ASYNC16(dst, src) \
    asm volatile("cp.async.cg.shared.global [%0], [%1], 16;\n" :: "r"(dst), "l"(src))
#define CP_ASYNC_COMMIT() asm volatile("cp.async.commit_group;\n" ::: "memory")
#define CP_ASYNC_WAIT(n)  asm volatile("cp.async.wait_group %0;\n" :: "n"(n) : "memory")

__device__ __forceinline__ uint32_t swz64(uint32_t byte_off) {
    return byte_off ^ ((byte_off >> 3) & 0x30);
}

__device__ __forceinline__ void ldmatrix_x4(uint32_t r[4], uint32_t addr) {
    asm volatile("ldmatrix.sync.aligned.m8n8.x4.shared.b16 {%0,%1,%2,%3}, [%4];"
                 : "=r"(r[0]), "=r"(r[1]), "=r"(r[2]), "=r"(r[3]) : "r"(addr));
}

__device__ __forceinline__ void mma_f16(float c[4], const uint32_t a[4],
                                        uint32_t b0, uint32_t b1) {
    asm volatile(
        "mma.sync.aligned.m16n8k16.row.col.f32.f16.f16.f32 "
        "{%0,%1,%2,%3}, {%4,%5,%6,%7}, {%8,%9}, {%0,%1,%2,%3};"
        : "+f"(c[0]), "+f"(c[1]), "+f"(c[2]), "+f"(c[3])
        : "r"(a[0]), "r"(a[1]), "r"(a[2]), "r"(a[3]), "r"(b0), "r"(b1));
}

// ===================== GEMM config =====================
static constexpr int BM = 128, BN = 128, BK = 32, STAGES = 4, NTHREADS = 256;
static constexpr int A_STAGE_BYTES = BM * BK * 2;
static constexpr int B_STAGE_BYTES = BN * BK * 2;
static constexpr int STAGE_BYTES   = A_STAGE_BYTES + B_STAGE_BYTES;
static constexpr int SMEM_BIAS     = 0;       // 128 floats
static constexpr int SMEM_W3      = 512;      // 128*6 floats (fused kernel only)
static constexpr int SMEM_TILES    = 4096;
static constexpr int SMEM_TOTAL    = SMEM_TILES + STAGES * STAGE_BYTES; // 69632

// D[m,n] = sum_k A[m,k] * BT[n*ldb + k] (+ bias[n]) (optional ReLU)
// out_mode: 0 = fp16 D (ld N), 1 = fp32 D (ld N).
// A K-split: k < ksplit -> A0 (lda0) else A1 (lda1, k-ksplit). ksplit % BK == 0.
// grid.z batching: az = za_elems * (za_and1 ? (z&1) : z) added to A0/A1;
//                  BT += zb_elems*z; D += zd_elems*z (elements of out dtype).
__global__ void __launch_bounds__(NTHREADS, 2)
gemm_f16(const __half* __restrict__ A0, const __half* __restrict__ A1,
         int ksplit, int lda0, int lda1,
         const __half* __restrict__ BT, int ldb, const float* __restrict__ bias,
         void* __restrict__ D, int out_mode, int N, int K, int do_relu,
         int za_elems, int za_and1, int zb_elems, size_t zd_elems)
{
    extern __shared__ char smem[];
    float* sb_bias = (float*)(smem + SMEM_BIAS);
    const uint32_t stile = smem_u32(smem) + SMEM_TILES;
    const int tid  = threadIdx.x;
    const int wid  = tid >> 5;
    const int lane = tid & 31;
    const int g    = lane >> 2;
    const int t    = lane & 3;
    const int m0 = blockIdx.y * BM;
    const int n0 = blockIdx.x * BN;
    const int warp_m = (wid >> 2) * 64;
    const int warp_n = (wid & 3) * 32;

    const int bz = blockIdx.z;
    const size_t az = (size_t)za_elems * (za_and1 ? (bz & 1) : bz);
    A0 += az;  A1 += az;
    BT += (size_t)zb_elems * bz;
    const size_t d_off = zd_elems * bz;

    if (tid < BN) sb_bias[tid] = bias ? bias[n0 + tid] : 0.f;

    const int KB = K / BK;

    auto load_stage = [&](int kb) {
        const int s = kb & (STAGES - 1);
        const int k0 = kb * BK;
        const uint32_t a_base = stile + s * STAGE_BYTES;
        const uint32_t b_base = a_base + A_STAGE_BYTES;
        #pragma unroll
        for (int j = 0; j < 2; j++) {
            int idx = tid + j * NTHREADS;
            int row = idx >> 2;
            int c   = idx & 3;
            int kg  = k0 + (c << 3);
            const __half* src = (kg < ksplit)
                ? (A0 + (size_t)(m0 + row) * lda0 + kg)
                : (A1 + (size_t)(m0 + row) * lda1 + (kg - ksplit));
            uint32_t dst = a_base + swz64((uint32_t)(row * 64 + (c << 4)));
            CP_ASYNC16(dst, src);
        }
        #pragma unroll
        for (int j = 0; j < 2; j++) {
            int idx = tid + j * NTHREADS;
            int row = idx >> 2;
            int c   = idx & 3;
            const __half* src = BT + (size_t)(n0 + row) * ldb + k0 + (c << 3);
            uint32_t dst = b_base + swz64((uint32_t)(row * 64 + (c << 4)));
            CP_ASYNC16(dst, src);
        }
        CP_ASYNC_COMMIT();
    };

    float acc[4][4][4];
    #pragma unroll
    for (int mt = 0; mt < 4; mt++)
        #pragma unroll
        for (int nt = 0; nt < 4; nt++)
            #pragma unroll
            for (int r = 0; r < 4; r++) acc[mt][nt][r] = 0.f;

    const int lm_row = (lane & 8) + (lane & 7);
    const int lm_k   = (lane & 16) >> 1;

    load_stage(0); load_stage(1); load_stage(2);

    for (int kb = 0; kb < KB; kb++) {
        if (kb < KB - 3) { CP_ASYNC_WAIT(2); } else { CP_ASYNC_WAIT(0); }
        __syncthreads();
        if (kb + 3 < KB) load_stage(kb + 3);

        const int s = kb & (STAGES - 1);
        const uint32_t As = stile + s * STAGE_BYTES;
        const uint32_t Bs = As + A_STAGE_BYTES;

        #pragma unroll
        for (int ks = 0; ks < 2; ks++) {
            const int kk = ks * 16;
            uint32_t am[4][4], bm[2][4];
            #pragma unroll
            for (int mt = 0; mt < 4; mt++) {
                int row = warp_m + mt * 16 + lm_row;
                ldmatrix_x4(am[mt], As + swz64((uint32_t)(row * 64 + (kk + lm_k) * 2)));
            }
            #pragma unroll
            for (int pr = 0; pr < 2; pr++) {
                int row = warp_n + pr * 16 + lm_row;
                ldmatrix_x4(bm[pr], Bs + swz64((uint32_t)(row * 64 + (kk + lm_k) * 2)));
            }
            #pragma unroll
            for (int mt = 0; mt < 4; mt++)
                #pragma unroll
                for (int nt = 0; nt < 4; nt++)
                    mma_f16(acc[mt][nt], am[mt], bm[nt >> 1][nt & 1], bm[nt >> 1][(nt & 1) + 2]);
        }
    }

    // epilogue
    #pragma unroll
    for (int mt = 0; mt < 4; mt++) {
        const int row = m0 + warp_m + mt * 16 + g;
        #pragma unroll
        for (int nt = 0; nt < 4; nt++) {
            const int cb = warp_n + nt * 8 + t * 2;
            const int col = n0 + cb;
            float b0 = sb_bias[cb], b1 = sb_bias[cb + 1];
            float2 v0 = make_float2(acc[mt][nt][0] + b0, acc[mt][nt][1] + b1);
            float2 v1 = make_float2(acc[mt][nt][2] + b0, acc[mt][nt][3] + b1);
            if (do_relu) {
                v0.x = fmaxf(v0.x, 0.f); v0.y = fmaxf(v0.y, 0.f);
                v1.x = fmaxf(v1.x, 0.f); v1.y = fmaxf(v1.y, 0.f);
            }
            if (out_mode == 0) {
                __half* Dh = (__half*)D + d_off;
                *reinterpret_cast<__half2*>(Dh + (size_t)row * N + col)       = __floats2half2_rn(v0.x, v0.y);
                *reinterpret_cast<__half2*>(Dh + (size_t)(row + 8) * N + col) = __floats2half2_rn(v1.x, v1.y);
            } else {
                float* Df = (float*)D + d_off;
                *reinterpret_cast<float2*>(Df + (size_t)row * N + col)       = v0;
                *reinterpret_cast<float2*>(Df + (size_t)(row + 8) * N + col) = v1;
            }
        }
    }
}

// ============ fused h2+final: pb[bx][m][0:6] = relu(h1@w2+b2)[m, n0:n0+128] @ w3[n0:n0+128] ====
__global__ void __launch_bounds__(NTHREADS, 2)
gemm_h2_fused(const __half* __restrict__ A, const __half* __restrict__ BT,
              const float* __restrict__ bias, const float* __restrict__ w3,
              float* __restrict__ pb)
{
    extern __shared__ char smem[];
    float* sb_bias = (float*)(smem + SMEM_BIAS);
    float* w3s     = (float*)(smem + SMEM_W3);     // [128][6]
    const uint32_t stile = smem_u32(smem) + SMEM_TILES;
    const int tid  = threadIdx.x;
    const int wid  = tid >> 5;
    const int lane = tid & 31;
    const int g    = lane >> 2;
    const int t    = lane & 3;
    const int m0 = blockIdx.y * BM;
    const int n0 = blockIdx.x * BN;
    const int warp_m = (wid >> 2) * 64;
    const int warp_n = (wid & 3) * 32;
    const int K = U3, ldab = U3;

    if (tid < BN) sb_bias[tid] = bias[n0 + tid];
    for (int i = tid; i < BN * ACT; i += NTHREADS)
        w3s[i] = w3[(size_t)(n0 + i / ACT) * ACT + (i % ACT)];

    const int KB = K / BK;   // 16

    auto load_stage = [&](int kb) {
        const int s = kb & (STAGES - 1);
        const int k0 = kb * BK;
        const uint32_t a_base = stile + s * STAGE_BYTES;
        const uint32_t b_base = a_base + A_STAGE_BYTES;
        #pragma unroll
        for (int j = 0; j < 2; j++) {
            int idx = tid + j * NTHREADS;
            int row = idx >> 2;
            int c   = idx & 3;
            const __half* src = A + (size_t)(m0 + row) * ldab + k0 + (c << 3);
            uint32_t dst = a_base + swz64((uint32_t)(row * 64 + (c << 4)));
            CP_ASYNC16(dst, src);
        }
        #pragma unroll
        for (int j = 0; j < 2; j++) {
            int idx = tid + j * NTHREADS;
            int row = idx >> 2;
            int c   = idx & 3;
            const __half* src = BT + (size_t)(n0 + row) * ldab + k0 + (c << 3);
            uint32_t dst = b_base + swz64((uint32_t)(row * 64 + (c << 4)));
            CP_ASYNC16(dst, src);
        }
        CP_ASYNC_COMMIT();
    };

    float acc[4][4][4];
    #pragma unroll
    for (int mt = 0; mt < 4; mt++)
        #pragma unroll
        for (int nt = 0; nt < 4; nt++)
            #pragma unroll
            for (int r = 0; r < 4; r++) acc[mt][nt][r] = 0.f;

    const int lm_row = (lane & 8) + (lane & 7);
    const int lm_k   = (lane & 16) >> 1;

    load_stage(0); load_stage(1); load_stage(2);

    for (int kb = 0; kb < KB; kb++) {
        if (kb < KB - 3) { CP_ASYNC_WAIT(2); } else { CP_ASYNC_WAIT(0); }
        __syncthreads();
        if (kb + 3 < KB) load_stage(kb + 3);

        const int s = kb & (STAGES - 1);
        const uint32_t As = stile + s * STAGE_BYTES;
        const uint32_t Bs = As + A_STAGE_BYTES;

        #pragma unroll
        for (int ks = 0; ks < 2; ks++) {
            const int kk = ks * 16;
            uint32_t am[4][4], bm[2][4];
            #pragma unroll
            for (int mt = 0; mt < 4; mt++) {
                int row = warp_m + mt * 16 + lm_row;
                ldmatrix_x4(am[mt], As + swz64((uint32_t)(row * 64 + (kk + lm_k) * 2)));
            }
            #pragma unroll
            for (int pr = 0; pr < 2; pr++) {
                int row = warp_n + pr * 16 + lm_row;
                ldmatrix_x4(bm[pr], Bs + swz64((uint32_t)(row * 64 + (kk + lm_k) * 2)));
            }
            #pragma unroll
            for (int mt = 0; mt < 4; mt++)
                #pragma unroll
                for (int nt = 0; nt < 4; nt++)
                    mma_f16(acc[mt][nt], am[mt], bm[nt >> 1][nt & 1], bm[nt >> 1][(nt & 1) + 2]);
        }
    }

    // fused epilogue: v = relu(acc + bias); P[row][n] += v * w3s  (deterministic)
    float* Pw = (float*)(smem + SMEM_TILES);   // [4][128][6], reuses tile region
    __syncthreads();
    #pragma unroll
    for (int mt = 0; mt < 4; mt++) {
        float s0[ACT] = {0,0,0,0,0,0}, s1[ACT] = {0,0,0,0,0,0};
        #pragma unroll
        for (int nt = 0; nt < 4; nt++) {
            const int cb = warp_n + nt * 8 + t * 2;
            float b0 = sb_bias[cb], b1v = sb_bias[cb + 1];
            float v00 = fmaxf(acc[mt][nt][0] + b0,  0.f);
            float v01 = fmaxf(acc[mt][nt][1] + b1v, 0.f);
            float v10 = fmaxf(acc[mt][nt][2] + b0,  0.f);
            float v11 = fmaxf(acc[mt][nt][3] + b1v, 0.f);
            #pragma unroll
            for (int n = 0; n < ACT; n++) {
                float w0 = w3s[cb * ACT + n], w1v = w3s[(cb + 1) * ACT + n];
                s0[n] += v00 * w0 + v01 * w1v;
                s1[n] += v10 * w0 + v11 * w1v;
            }
        }
        #pragma unroll
        for (int n = 0; n < ACT; n++) {
            s0[n] += __shfl_xor_sync(0xffffffffu, s0[n], 1);
            s0[n] += __shfl_xor_sync(0xffffffffu, s0[n], 2);
            s1[n] += __shfl_xor_sync(0xffffffffu, s1[n], 1);
            s1[n] += __shfl_xor_sync(0xffffffffu, s1[n], 2);
        }
        if (t == 0) {
            const int wn = wid & 3;
            const int rl = warp_m + mt * 16 + g;
            #pragma unroll
            for (int n = 0; n < ACT; n++) {
                Pw[(wn * 128 + rl) * ACT + n]     = s0[n];
                Pw[(wn * 128 + rl + 8) * ACT + n] = s1[n];
            }
        }
    }
    __syncthreads();
    if (tid < 128) {
        #pragma unroll
        for (int n = 0; n < ACT; n++) {
            float s = Pw[(0 * 128 + tid) * ACT + n] + Pw[(1 * 128 + tid) * ACT + n]
                    + Pw[(2 * 128 + tid) * ACT + n] + Pw[(3 * 128 + tid) * ACT + n];
            pb[((size_t)blockIdx.x * BATCH + m0 + tid) * 8 + n] = s;
        }
    }
}

// out[m][n] = relu(b3[n] + sum_bx pb[bx][m][n])
__global__ void combine_out(const float* __restrict__ pb, const float* __restrict__ b3,
                            float* __restrict__ out)
{
    int idx = blockIdx.x * blockDim.x + threadIdx.x;
    if (idx >= BATCH * ACT) return;
    int m = idx / ACT, n = idx % ACT;
    float s = b3[n];
    #pragma unroll
    for (int bx = 0; bx < 4; bx++)
        s += pb[((size_t)bx * BATCH + m) * 8 + n];
    out[(size_t)m * ACT + n] = fmaxf(s, 0.f);
}

// ===================== weight prep kernels =====================
// wt[n][k] = f16(w[k][n] * mask[n*mask_ld + mask_koff + k])
__global__ void transpose_mask(const float* __restrict__ w, const float* __restrict__ mask,
                               __half* __restrict__ wt, int K, int N, int mask_ld, int mask_koff)
{
    __shared__ float tile[32][33];
    const int k0 = blockIdx.x * 32, n0 = blockIdx.y * 32;
    const int tx = threadIdx.x, ty = threadIdx.y;
    #pragma unroll
    for (int j = 0; j < 32; j += 8)
        tile[ty + j][tx] = w[(size_t)(k0 + ty + j) * N + n0 + tx];
    __syncthreads();
    #pragma unroll
    for (int j = 0; j < 32; j += 8) {
        const int n = n0 + ty + j, k = k0 + tx;
        float v = tile[tx][ty + j];
        if (mask) v *= mask[(size_t)n * mask_ld + mask_koff + k];
        wt[(size_t)n * K + k] = __float2half_rn(v);
    }
}

__global__ void transpose_split_w1(const float* __restrict__ w, __half* __restrict__ w1s,
                                   int K, int N)
{
    __shared__ float tile[32][33];
    const int k0 = blockIdx.x * 32, n0 = blockIdx.y * 32;
    const int tx = threadIdx.x, ty = threadIdx.y;
    #pragma unroll
    for (int j = 0; j < 32; j += 8)
        tile[ty + j][tx] = w[(size_t)(k0 + ty + j) * N + n0 + tx];
    __syncthreads();
    #pragma unroll
    for (int j = 0; j < 32; j += 8) {
        const int n = n0 + ty + j, k = k0 + tx;
        float v = tile[tx][ty + j];
        __half hi = __float2half_rn(v);
        __half lo = __float2half_rn(v - __half2float(hi));
        w1s[(size_t)n * (2 * K) + k]     = hi;
        w1s[(size_t)n * (2 * K) + K + k] = lo;
    }
}

__global__ void mask_apply_nt(const float* __restrict__ w, const float* __restrict__ mask,
                              int mstride, __half* __restrict__ out, int J)
{
    __shared__ float mt[32][33];
    const int i0 = blockIdx.y * 32, j0 = blockIdx.x * 32;
    const int tx = threadIdx.x, ty = threadIdx.y;
    #pragma unroll
    for (int jj = 0; jj < 32; jj += 8)
        mt[ty + jj][tx] = mask[(size_t)(j0 + ty + jj) * mstride + i0 + tx];
    __syncthreads();
    #pragma unroll
    for (int jj = 0; jj < 32; jj += 8) {
        const int i = i0 + ty + jj, j = j0 + tx;
        out[(size_t)i * J + j] = __float2half_rn(w[(size_t)i * J + j] * mt[tx][ty + jj]);
    }
}

__global__ void mask_apply_nt_f32(const float* __restrict__ w, const float* __restrict__ mask,
                                  int mstride, float* __restrict__ out, int J)
{
    __shared__ float mt[32][33];
    const int i0 = blockIdx.y * 32, j0 = blockIdx.x * 32;
    const int tx = threadIdx.x, ty = threadIdx.y;
    #pragma unroll
    for (int jj = 0; jj < 32; jj += 8)
        mt[ty + jj][tx] = mask[(size_t)(j0 + ty + jj) * mstride + i0 + tx];
    __syncthreads();
    #pragma unroll
    for (int jj = 0; jj < 32; jj += 8) {
        const int i = i0 + ty + jj, j = j0 + tx;
        out[(size_t)i * J + j] = w[(size_t)i * J + j] * mt[tx][ty + jj];
    }
}

// weffs[i][ hi | hi | lo ] from p0+p1+wx (fp32 sum, deterministic).
__global__ void reduce_split3(const float* __restrict__ p, const float* __restrict__ wx,
                              __half* __restrict__ dst, int J)
{
    const size_t PSTRIDE = (size_t)DGPE_IN * DGPI_OUT;
    const int i = blockIdx.y;
    const int j = (blockIdx.x * blockDim.x + threadIdx.x) * 4;
    const size_t src = (size_t)i * J + j;
    float4 a = *reinterpret_cast<const float4*>(p + src);
    float4 b = *reinterpret_cast<const float4*>(p + PSTRIDE + src);
    float4 c = *reinterpret_cast<const float4*>(wx + src);
    float v0 = a.x + b.x + c.x, v1 = a.y + b.y + c.y;
    float v2 = a.z + b.z + c.z, v3 = a.w + b.w + c.w;
    __half2 h01 = __floats2half2_rn(v0, v1);
    __half2 h23 = __floats2half2_rn(v2, v3);
    __half2 l01 = __floats2half2_rn(v0 - __half2float(h01.x), v1 - __half2float(h01.y));
    __half2 l23 = __floats2half2_rn(v2 - __half2float(h23.x), v3 - __half2float(h23.y));
    const size_t base = (size_t)i * (3 * J);
    *reinterpret_cast<__half2*>(dst + base + j)             = h01;
    *reinterpret_cast<__half2*>(dst + base + j + 2)         = h23;
    *reinterpret_cast<__half2*>(dst + base + J + j)         = h01;
    *reinterpret_cast<__half2*>(dst + base + J + j + 2)     = h23;
    *reinterpret_cast<__half2*>(dst + base + 2 * J + j)     = l01;
    *reinterpret_cast<__half2*>(dst + base + 2 * J + j + 2) = l23;
}

// wfull_h = f16(sum of 3 partials), vectorized; stride = U3*DGPE_IN per partial
__global__ void reduce3q_f16(const float* __restrict__ q, __half* __restrict__ out)
{
    const size_t STRIDE = (size_t)U3 * DGPE_IN;
    int i = (blockIdx.x * blockDim.x + threadIdx.x) * 4;
    float4 s = *reinterpret_cast<const float4*>(q + i);
    #pragma unroll
    for (int z = 1; z < 3; z++) {
        float4 a = *reinterpret_cast<const float4*>(q + z * STRIDE + i);
        s.x += a.x; s.y += a.y; s.z += a.z; s.w += a.w;
    }
    *reinterpret_cast<__half2*>(out + i)     = __floats2half2_rn(s.x, s.y);
    *reinterpret_cast<__half2*>(out + i + 2) = __floats2half2_rn(s.z, s.w);
}

__global__ void bias_eff_kernel(const float* __restrict__ gpi_w, const float* __restrict__ gpi_mask,
                                const float* __restrict__ gpe_b,
                                const float* __restrict__ gpi_b, float* __restrict__ be)
{
    const int n = blockIdx.x * 8 + (threadIdx.x >> 5);
    const int lane = threadIdx.x & 31;
    const float* mrow = gpi_mask + (size_t)n * DGPI_IN + DGPE_IN;
    float s0 = 0.f, s1 = 0.f;
    for (int j = lane; j < DGPE_OUT; j += 64) {
        s0 += gpi_w[(size_t)(DGPE_IN + j) * DGPI_OUT + n] * mrow[j] * gpe_b[j];
        int j2 = j + 32;
        s1 += gpi_w[(size_t)(DGPE_IN + j2) * DGPI_OUT + n] * mrow[j2] * gpe_b[j2];
    }
    float s = s0 + s1;
    #pragma unroll
    for (int off = 16; off; off >>= 1) s += __shfl_xor_sync(0xffffffffu, s, off);
    if (lane == 0) be[n] = gpi_b[n] + s;
}

__global__ void bias_full_kernel(const float* __restrict__ be, const float* __restrict__ w1,
                                 const float* __restrict__ b1, float* __restrict__ bf)
{
    const int n = blockIdx.x * 8 + (threadIdx.x >> 5);
    const int lane = threadIdx.x & 31;
    float s0 = 0.f, s1 = 0.f;
    for (int j = lane; j < DGPI_OUT; j += 64) {
        s0 += be[j] * w1[(size_t)j * U3 + n];
        s1 += be[j + 32] * w1[(size_t)(j + 32) * U3 + n];
    }
    float s = s0 + s1;
    #pragma unroll
    for (int off = 16; off; off >>= 1) s += __shfl_xor_sync(0xffffffffu, s, off);
    if (lane == 0) bf[n] = b1[n] + s;
}

__global__ void convert_f2h(const float* __restrict__ src, __half* __restrict__ dst, int n)
{
    int i = (blockIdx.x * blockDim.x + threadIdx.x) * 4;
    if (i < n) {
        float4 v = *reinterpret_cast<const float4*>(src + i);
        *reinterpret_cast<__half2*>(dst + i)     = __floats2half2_rn(v.x, v.y);
        *reinterpret_cast<__half2*>(dst + i + 2) = __floats2half2_rn(v.z, v.w);
    }
}

// ===================== launch =====================
extern "C" void kernel_launch(void* const* d_in, const int* in_sizes, int n_in,
                              void* d_out, int out_size)
{
    const float* x        = (const float*)d_in[0];
    const float* gpe_mask = (const float*)d_in[1];
    const float* gpe_w    = (const float*)d_in[2];
    const float* gpe_b    = (const float*)d_in[3];
    const float* gpi_mask = (const float*)d_in[4];
    const float* gpi_w    = (const float*)d_in[5];
    const float* gpi_b    = (const float*)d_in[6];
    const float* w1       = (const float*)d_in[7];
    const float* b1       = (const float*)d_in[8];
    const float* w2       = (const float*)d_in[9];
    const float* b2       = (const float*)d_in[10];
    const float* w3       = (const float*)d_in[11];
    const float* b3       = (const float*)d_in[12];
    float* out = (float*)d_out;

    __half *xh, *wt_gpiB, *wm_gpe, *weffs, *w1s, *wfull_h, *wt_w2, *h1;
    float *wx32, *we_p, *wf_q, *bias_eff, *bias_full, *pb;
    cudaGetSymbolAddress((void**)&xh,        g_xh);
    cudaGetSymbolAddress((void**)&wt_gpiB,   g_wt_gpiB);
    cudaGetSymbolAddress((void**)&wm_gpe,    g_wm_gpe);
    cudaGetSymbolAddress((void**)&wx32,      g_wx32);
    cudaGetSymbolAddress((void**)&we_p,      g_we_p);
    cudaGetSymbolAddress((void**)&weffs,     g_weffs);
    cudaGetSymbolAddress((void**)&w1s,       g_w1s);
    cudaGetSymbolAddress((void**)&wf_q,      g_wf_q);
    cudaGetSymbolAddress((void**)&wfull_h,   g_wfull_h);
    cudaGetSymbolAddress((void**)&bias_eff,  g_bias_eff);
    cudaGetSymbolAddress((void**)&bias_full, g_bias_full);
    cudaGetSymbolAddress((void**)&wt_w2,     g_wt_w2);
    cudaGetSymbolAddress((void**)&h1,        g_h1);
    cudaGetSymbolAddress((void**)&pb,        g_pb);

    cudaFuncSetAttribute(gemm_f16,      cudaFuncAttributeMaxDynamicSharedMemorySize, SMEM_TOTAL);
    cudaFuncSetAttribute(gemm_h2_fused, cudaFuncAttributeMaxDynamicSharedMemorySize, SMEM_TOTAL);

    // 3 streams max — proven-safe resource footprint.
    static cudaStream_t sA = nullptr, sB = nullptr, sC = nullptr;
    static cudaEvent_t evRoot, evGpi, evWx, evW1s, evW2, evWfull, evJoin, evH2b;
    if (sA == nullptr) {
        cudaStreamCreateWithFlags(&sA, cudaStreamNonBlocking);
        cudaStreamCreateWithFlags(&sB, cudaStreamNonBlocking);
        cudaStreamCreateWithFlags(&sC, cudaStreamNonBlocking);
        cudaEventCreateWithFlags(&evRoot,  cudaEventDisableTiming);
        cudaEventCreateWithFlags(&evGpi,   cudaEventDisableTiming);
        cudaEventCreateWithFlags(&evWx,    cudaEventDisableTiming);
        cudaEventCreateWithFlags(&evW1s,   cudaEventDisableTiming);
        cudaEventCreateWithFlags(&evW2,    cudaEventDisableTiming);
        cudaEventCreateWithFlags(&evWfull, cudaEventDisableTiming);
        cudaEventCreateWithFlags(&evJoin,  cudaEventDisableTiming);
        cudaEventCreateWithFlags(&evH2b,   cudaEventDisableTiming);
    }

    const dim3 tb(32, 8);
    const int nx = BATCH * DGPE_IN;
    const int KH = DGPE_OUT / 2;   // 768 K-half for W_eff split
    const size_t QSTRIDE = (size_t)U3 * DGPE_IN;
    const size_t PSTRIDE = (size_t)DGPE_IN * DGPI_OUT;
    const int MHALF = BATCH / 2;

    // ---- fork ----
    cudaEventRecord(evRoot, 0);
    cudaStreamWaitEvent(sA, evRoot, 0);
    cudaStreamWaitEvent(sB, evRoot, 0);
    cudaStreamWaitEvent(sC, evRoot, 0);

    // L: x conversion (big, independent), then off-path bias chain
    convert_f2h<<<(nx / 4 + 255) / 256, 256>>>(x, xh, nx);
    bias_eff_kernel<<<DGPI_OUT / 8, 256>>>(gpi_w, gpi_mask, gpe_b, gpi_b, bias_eff);
    bias_full_kernel<<<U3 / 8, 256>>>(bias_eff, w1, b1, bias_full);

    // sA: HALF gpi transpose (Wg block)
    transpose_mask<<<dim3(DGPE_OUT / 32, DGPI_OUT / 32), tb, 0, sA>>>(
        gpi_w + (size_t)DGPE_IN * DGPI_OUT, gpi_mask, wt_gpiB,
        DGPE_OUT, DGPI_OUT, DGPI_IN, DGPE_IN);
    cudaEventRecord(evGpi, sA);

    // sC: wx32, w1 split, w2 transpose
    mask_apply_nt_f32<<<dim3(DGPI_OUT / 32, DGPE_IN / 32), tb, 0, sC>>>(gpi_w, gpi_mask, DGPI_IN, wx32, DGPI_OUT);
    cudaEventRecord(evWx, sC);
    transpose_split_w1<<<dim3(DGPI_OUT / 32, U3 / 32), tb, 0, sC>>>(w1, w1s, DGPI_OUT, U3);
    cudaEventRecord(evW1s, sC);
    transpose_mask<<<dim3(U3 / 32, U3 / 32), tb, 0, sC>>>(w2, nullptr, wt_w2, U3, U3, U3, 0);
    cudaEventRecord(evW2, sC);

    // sB: gpe mask -> merged W_eff split-K (grid.z=2) -> reduce -> merged W_full (grid.z=3)
    mask_apply_nt<<<dim3(DGPE_OUT / 32, DGPE_IN / 32), tb, 0, sB>>>(gpe_w, gpe_mask, DGPE_IN, wm_gpe, DGPE_OUT);
    cudaStreamWaitEvent(sB, evGpi, 0);
    gemm_f16<<<dim3(DGPI_OUT / BN, DGPE_IN / BM, 2), NTHREADS, SMEM_TOTAL, sB>>>(
        wm_gpe, wm_gpe, KH, DGPE_OUT, DGPE_OUT,
        wt_gpiB, DGPE_OUT, nullptr, we_p, 1, DGPI_OUT, KH, 0,
        KH, 0, KH, PSTRIDE);
    cudaStreamWaitEvent(sB, evWx, 0);
    reduce_split3<<<dim3(DGPI_OUT / (128 * 4), DGPE_IN), 128, 0, sB>>>(
        we_p, wx32, weffs, DGPI_OUT);
    cudaStreamWaitEvent(sB, evW1s, 0);
    // z0: w1hi x weff_hi, z1: w1lo x weff_hi, z2: w1hi x weff_lo
    gemm_f16<<<dim3(DGPE_IN / BN, U3 / BM, 3), NTHREADS, SMEM_TOTAL, sB>>>(
        w1s, w1s, DGPI_OUT, 2 * DGPI_OUT, 2 * DGPI_OUT,
        weffs, 3 * DGPI_OUT, nullptr, wf_q, 1, DGPE_IN, DGPI_OUT, 0,
        DGPI_OUT, 1, DGPI_OUT, QSTRIDE);
    reduce3q_f16<<<(int)(QSTRIDE / 4 / 256), 256, 0, sB>>>(wf_q, wfull_h);
    cudaEventRecord(evWfull, sB);

    // ---- join + pipelined h1/h2 over batch halves ----
    cudaStreamWaitEvent(0, evWfull, 0);
    cudaStreamWaitEvent(0, evW2, 0);
    cudaEventRecord(evJoin, 0);
    cudaStreamWaitEvent(sA, evJoin, 0);

    // h1a (rows 0..MHALF) on legacy; h1b on sA — run concurrently
    gemm_f16<<<dim3(U3 / BN, MHALF / BM), NTHREADS, SMEM_TOTAL>>>(
        xh, xh, DGPE_IN, DGPE_IN, DGPE_IN,
        wfull_h, DGPE_IN, bias_full, h1, 0, U3, DGPE_IN, 1, 0, 0, 0, 0);
    gemm_f16<<<dim3(U3 / BN, MHALF / BM), NTHREADS, SMEM_TOTAL, sA>>>(
        xh + (size_t)MHALF * DGPE_IN, xh + (size_t)MHALF * DGPE_IN, DGPE_IN, DGPE_IN, DGPE_IN,
        wfull_h, DGPE_IN, bias_full, h1 + (size_t)MHALF * U3, 0, U3, DGPE_IN, 1, 0, 0, 0, 0);

    // h2a behind h1a (fills chip during h1b tail); h2b behind h1b
    gemm_h2_fused<<<dim3(U3 / BN, MHALF / BM), NTHREADS, SMEM_TOTAL>>>(
        h1, wt_w2, b2, w3, pb);
    gemm_h2_fused<<<dim3(U3 / BN, MHALF / BM), NTHREADS, SMEM_TOTAL, sA>>>(
        h1 + (size_t)MHALF * U3, wt_w2, b2, w3, pb + (size_t)MHALF * 8);
    cudaEventRecord(evH2b, sA);

    // out = relu(sum pb + b3)
    cudaStreamWaitEvent(0, evH2b, 0);
    combine_out<<<(BATCH * ACT + 255) / 256, 256>>>(pb, b3, out);
}

// round 16
// speedup vs baseline: 1.4473x; 1.0166x over previous
#include <cuda_runtime.h>
#include <cuda_fp16.h>
#include <cstdint>

// ===================== problem dims =====================
static constexpr int BATCH    = 16384;
static constexpr int DGPE_IN  = 1536;
static constexpr int DGPE_OUT = 1536;
static constexpr int DGPI_IN  = 3072;
static constexpr int DGPI_OUT = 1536;
static constexpr int U3       = 512;
static constexpr int ACT      = 6;

// ===================== device scratch (no cudaMalloc allowed) =====================
__device__ __half g_xh     [(size_t)BATCH * DGPE_IN];        // x as fp16
__device__ __half g_wt_gpiB[DGPI_OUT * DGPE_OUT];            // [j][k] masked Wg^T (gpi cols 1536:3072)
__device__ __half g_wm_gpe [DGPE_IN * DGPE_OUT];             // [i][k] masked gpe W (non-transposed)
__device__ float  g_wx32   [DGPE_IN * DGPI_OUT];             // [i][j] masked Wx (fp32, exact)
__device__ float  g_we_p   [(size_t)2 * DGPE_IN * DGPI_OUT]; // W_eff K-split partials (contiguous)
__device__ __half g_weffs  [(size_t)DGPE_IN * 3 * DGPI_OUT]; // [i][ hi | hi | lo ]
__device__ __half g_w1s    [U3 * 2 * DGPI_OUT];              // [n][ hi | lo ]
__device__ float  g_wf_q   [(size_t)3 * U3 * DGPE_IN];       // W_full 3-way partials (fp32)
__device__ __half g_wfull_h[U3 * DGPE_IN];                   // [n][i] fp16 final
__device__ float  g_bias_eff[DGPI_OUT];
__device__ float  g_bias_full[U3];
__device__ __half g_wt_w2  [U3 * U3];
__device__ __half g_h1[(size_t)BATCH * U3];
__device__ float  g_pb[(size_t)4 * BATCH * 8];               // fused-out partials

// ===================== helpers =====================
__device__ __forceinline__ uint32_t smem_u32(const void* p) {
    return (uint32_t)__cvta_generic_to_shared(p);
}
#define CP_ASYNC16(dst, src) \
    asm volatile("cp.async.cg.shared.global [%0], [%1], 16;\n" :: "r"(dst), "l"(src))
#define CP_ASYNC_COMMIT() asm volatile("cp.async.commit_group;\n" ::: "memory")
#define CP_ASYNC_WAIT(n)  asm volatile("cp.async.wait_group %0;\n" :: "n"(n) : "memory")

__device__ __forceinline__ uint32_t swz64(uint32_t byte_off) {
    return byte_off ^ ((byte_off >> 3) & 0x30);
}

__device__ __forceinline__ void ldmatrix_x4(uint32_t r[4], uint32_t addr) {
    asm volatile("ldmatrix.sync.aligned.m8n8.x4.shared.b16 {%0,%1,%2,%3}, [%4];"
                 : "=r"(r[0]), "=r"(r[1]), "=r"(r[2]), "=r"(r[3]) : "r"(addr));
}

__device__ __forceinline__ void mma_f16(float c[4], const uint32_t a[4],
                                        uint32_t b0, uint32_t b1) {
    asm volatile(
        "mma.sync.aligned.m16n8k16.row.col.f32.f16.f16.f32 "
        "{%0,%1,%2,%3}, {%4,%5,%6,%7}, {%8,%9}, {%0,%1,%2,%3};"
        : "+f"(c[0]), "+f"(c[1]), "+f"(c[2]), "+f"(c[3])
        : "r"(a[0]), "r"(a[1]), "r"(a[2]), "r"(a[3]), "r"(b0), "r"(b1));
}

// ===================== GEMM config =====================
static constexpr int BM = 128, BN = 128, BK = 32, STAGES = 4, NTHREADS = 256;
static constexpr int A_STAGE_BYTES = BM * BK * 2;
static constexpr int B_STAGE_BYTES = BN * BK * 2;
static constexpr int STAGE_BYTES   = A_STAGE_BYTES + B_STAGE_BYTES;
static constexpr int SMEM_BIAS     = 0;       // 128 floats
static constexpr int SMEM_W3      = 512;      // 128*6 floats (fused kernel only)
static constexpr int SMEM_TILES    = 4096;
static constexpr int SMEM_TOTAL    = SMEM_TILES + STAGES * STAGE_BYTES; // 69632

// D[m,n] = sum_k A[m,k] * BT[n*ldb + k] (+ bias[n]) (optional ReLU)
// out_mode: 0 = fp16 D (ld N), 1 = fp32 D (ld N).
// A K-split: k < ksplit -> A0 (lda0) else A1 (lda1, k-ksplit). ksplit % BK == 0.
// grid.z batching: az = za_elems * (za_and1 ? (z&1) : z) added to A0/A1;
//                  BT += zb_elems*z; D += zd_elems*z (elements of out dtype).
__global__ void __launch_bounds__(NTHREADS, 2)
gemm_f16(const __half* __restrict__ A0, const __half* __restrict__ A1,
         int ksplit, int lda0, int lda1,
         const __half* __restrict__ BT, int ldb, const float* __restrict__ bias,
         void* __restrict__ D, int out_mode, int N, int K, int do_relu,
         int za_elems, int za_and1, int zb_elems, size_t zd_elems)
{
    extern __shared__ char smem[];
    float* sb_bias = (float*)(smem + SMEM_BIAS);
    const uint32_t stile = smem_u32(smem) + SMEM_TILES;
    const int tid  = threadIdx.x;
    const int wid  = tid >> 5;
    const int lane = tid & 31;
    const int g    = lane >> 2;
    const int t    = lane & 3;
    const int m0 = blockIdx.y * BM;
    const int n0 = blockIdx.x * BN;
    const int warp_m = (wid >> 2) * 64;
    const int warp_n = (wid & 3) * 32;

    const int bz = blockIdx.z;
    const size_t az = (size_t)za_elems * (za_and1 ? (bz & 1) : bz);
    A0 += az;  A1 += az;
    BT += (size_t)zb_elems * bz;
    const size_t d_off = zd_elems * bz;

    if (tid < BN) sb_bias[tid] = bias ? bias[n0 + tid] : 0.f;

    const int KB = K / BK;

    auto load_stage = [&](int kb) {
        const int s = kb & (STAGES - 1);
        const int k0 = kb * BK;
        const uint32_t a_base = stile + s * STAGE_BYTES;
        const uint32_t b_base = a_base + A_STAGE_BYTES;
        #pragma unroll
        for (int j = 0; j < 2; j++) {
            int idx = tid + j * NTHREADS;
            int row = idx >> 2;
            int c   = idx & 3;
            int kg  = k0 + (c << 3);
            const __half* src = (kg < ksplit)
                ? (A0 + (size_t)(m0 + row) * lda0 + kg)
                : (A1 + (size_t)(m0 + row) * lda1 + (kg - ksplit));
            uint32_t dst = a_base + swz64((uint32_t)(row * 64 + (c << 4)));
            CP_ASYNC16(dst, src);
        }
        #pragma unroll
        for (int j = 0; j < 2; j++) {
            int idx = tid + j * NTHREADS;
            int row = idx >> 2;
            int c   = idx & 3;
            const __half* src = BT + (size_t)(n0 + row) * ldb + k0 + (c << 3);
            uint32_t dst = b_base + swz64((uint32_t)(row * 64 + (c << 4)));
            CP_ASYNC16(dst, src);
        }
        CP_ASYNC_COMMIT();
    };

    float acc[4][4][4];
    #pragma unroll
    for (int mt = 0; mt < 4; mt++)
        #pragma unroll
        for (int nt = 0; nt < 4; nt++)
            #pragma unroll
            for (int r = 0; r < 4; r++) acc[mt][nt][r] = 0.f;

    const int lm_row = (lane & 8) + (lane & 7);
    const int lm_k   = (lane & 16) >> 1;

    load_stage(0); load_stage(1); load_stage(2);

    for (int kb = 0; kb < KB; kb++) {
        if (kb < KB - 3) { CP_ASYNC_WAIT(2); } else { CP_ASYNC_WAIT(0); }
        __syncthreads();
        if (kb + 3 < KB) load_stage(kb + 3);

        const int s = kb & (STAGES - 1);
        const uint32_t As = stile + s * STAGE_BYTES;
        const uint32_t Bs = As + A_STAGE_BYTES;

        #pragma unroll
        for (int ks = 0; ks < 2; ks++) {
            const int kk = ks * 16;
            uint32_t am[4][4], bm[2][4];
            #pragma unroll
            for (int mt = 0; mt < 4; mt++) {
                int row = warp_m + mt * 16 + lm_row;
                ldmatrix_x4(am[mt], As + swz64((uint32_t)(row * 64 + (kk + lm_k) * 2)));
            }
            #pragma unroll
            for (int pr = 0; pr < 2; pr++) {
                int row = warp_n + pr * 16 + lm_row;
                ldmatrix_x4(bm[pr], Bs + swz64((uint32_t)(row * 64 + (kk + lm_k) * 2)));
            }
            #pragma unroll
            for (int mt = 0; mt < 4; mt++)
                #pragma unroll
                for (int nt = 0; nt < 4; nt++)
                    mma_f16(acc[mt][nt], am[mt], bm[nt >> 1][nt & 1], bm[nt >> 1][(nt & 1) + 2]);
        }
    }

    // epilogue
    #pragma unroll
    for (int mt = 0; mt < 4; mt++) {
        const int row = m0 + warp_m + mt * 16 + g;
        #pragma unroll
        for (int nt = 0; nt < 4; nt++) {
            const int cb = warp_n + nt * 8 + t * 2;
            const int col = n0 + cb;
            float b0 = sb_bias[cb], b1 = sb_bias[cb + 1];
            float2 v0 = make_float2(acc[mt][nt][0] + b0, acc[mt][nt][1] + b1);
            float2 v1 = make_float2(acc[mt][nt][2] + b0, acc[mt][nt][3] + b1);
            if (do_relu) {
                v0.x = fmaxf(v0.x, 0.f); v0.y = fmaxf(v0.y, 0.f);
                v1.x = fmaxf(v1.x, 0.f); v1.y = fmaxf(v1.y, 0.f);
            }
            if (out_mode == 0) {
                __half* Dh = (__half*)D + d_off;
                *reinterpret_cast<__half2*>(Dh + (size_t)row * N + col)       = __floats2half2_rn(v0.x, v0.y);
                *reinterpret_cast<__half2*>(Dh + (size_t)(row + 8) * N + col) = __floats2half2_rn(v1.x, v1.y);
            } else {
                float* Df = (float*)D + d_off;
                *reinterpret_cast<float2*>(Df + (size_t)row * N + col)       = v0;
                *reinterpret_cast<float2*>(Df + (size_t)(row + 8) * N + col) = v1;
            }
        }
    }
}

// ============ fused h2+final: pb[bx][m][0:6] = relu(h1@w2+b2)[m, n0:n0+128] @ w3[n0:n0+128] ====
__global__ void __launch_bounds__(NTHREADS, 2)
gemm_h2_fused(const __half* __restrict__ A, const __half* __restrict__ BT,
              const float* __restrict__ bias, const float* __restrict__ w3,
              float* __restrict__ pb)
{
    extern __shared__ char smem[];
    float* sb_bias = (float*)(smem + SMEM_BIAS);
    float* w3s     = (float*)(smem + SMEM_W3);     // [128][6]
    const uint32_t stile = smem_u32(smem) + SMEM_TILES;
    const int tid  = threadIdx.x;
    const int wid  = tid >> 5;
    const int lane = tid & 31;
    const int g    = lane >> 2;
    const int t    = lane & 3;
    const int m0 = blockIdx.y * BM;
    const int n0 = blockIdx.x * BN;
    const int warp_m = (wid >> 2) * 64;
    const int warp_n = (wid & 3) * 32;
    const int K = U3, ldab = U3;

    if (tid < BN) sb_bias[tid] = bias[n0 + tid];
    for (int i = tid; i < BN * ACT; i += NTHREADS)
        w3s[i] = w3[(size_t)(n0 + i / ACT) * ACT + (i % ACT)];

    const int KB = K / BK;   // 16

    auto load_stage = [&](int kb) {
        const int s = kb & (STAGES - 1);
        const int k0 = kb * BK;
        const uint32_t a_base = stile + s * STAGE_BYTES;
        const uint32_t b_base = a_base + A_STAGE_BYTES;
        #pragma unroll
        for (int j = 0; j < 2; j++) {
            int idx = tid + j * NTHREADS;
            int row = idx >> 2;
            int c   = idx & 3;
            const __half* src = A + (size_t)(m0 + row) * ldab + k0 + (c << 3);
            uint32_t dst = a_base + swz64((uint32_t)(row * 64 + (c << 4)));
            CP_ASYNC16(dst, src);
        }
        #pragma unroll
        for (int j = 0; j < 2; j++) {
            int idx = tid + j * NTHREADS;
            int row = idx >> 2;
            int c   = idx & 3;
            const __half* src = BT + (size_t)(n0 + row) * ldab + k0 + (c << 3);
            uint32_t dst = b_base + swz64((uint32_t)(row * 64 + (c << 4)));
            CP_ASYNC16(dst, src);
        }
        CP_ASYNC_COMMIT();
    };

    float acc[4][4][4];
    #pragma unroll
    for (int mt = 0; mt < 4; mt++)
        #pragma unroll
        for (int nt = 0; nt < 4; nt++)
            #pragma unroll
            for (int r = 0; r < 4; r++) acc[mt][nt][r] = 0.f;

    const int lm_row = (lane & 8) + (lane & 7);
    const int lm_k   = (lane & 16) >> 1;

    load_stage(0); load_stage(1); load_stage(2);

    for (int kb = 0; kb < KB; kb++) {
        if (kb < KB - 3) { CP_ASYNC_WAIT(2); } else { CP_ASYNC_WAIT(0); }
        __syncthreads();
        if (kb + 3 < KB) load_stage(kb + 3);

        const int s = kb & (STAGES - 1);
        const uint32_t As = stile + s * STAGE_BYTES;
        const uint32_t Bs = As + A_STAGE_BYTES;

        #pragma unroll
        for (int ks = 0; ks < 2; ks++) {
            const int kk = ks * 16;
            uint32_t am[4][4], bm[2][4];
            #pragma unroll
            for (int mt = 0; mt < 4; mt++) {
                int row = warp_m + mt * 16 + lm_row;
                ldmatrix_x4(am[mt], As + swz64((uint32_t)(row * 64 + (kk + lm_k) * 2)));
            }
            #pragma unroll
            for (int pr = 0; pr < 2; pr++) {
                int row = warp_n + pr * 16 + lm_row;
                ldmatrix_x4(bm[pr], Bs + swz64((uint32_t)(row * 64 + (kk + lm_k) * 2)));
            }
            #pragma unroll
            for (int mt = 0; mt < 4; mt++)
                #pragma unroll
                for (int nt = 0; nt < 4; nt++)
                    mma_f16(acc[mt][nt], am[mt], bm[nt >> 1][nt & 1], bm[nt >> 1][(nt & 1) + 2]);
        }
    }

    // fused epilogue: v = relu(acc + bias); P[row][n] += v * w3s  (deterministic)
    float* Pw = (float*)(smem + SMEM_TILES);   // [4][128][6], reuses tile region
    __syncthreads();
    #pragma unroll
    for (int mt = 0; mt < 4; mt++) {
        float s0[ACT] = {0,0,0,0,0,0}, s1[ACT] = {0,0,0,0,0,0};
        #pragma unroll
        for (int nt = 0; nt < 4; nt++) {
            const int cb = warp_n + nt * 8 + t * 2;
            float b0 = sb_bias[cb], b1v = sb_bias[cb + 1];
            float v00 = fmaxf(acc[mt][nt][0] + b0,  0.f);
            float v01 = fmaxf(acc[mt][nt][1] + b1v, 0.f);
            float v10 = fmaxf(acc[mt][nt][2] + b0,  0.f);
            float v11 = fmaxf(acc[mt][nt][3] + b1v, 0.f);
            #pragma unroll
            for (int n = 0; n < ACT; n++) {
                float w0 = w3s[cb * ACT + n], w1v = w3s[(cb + 1) * ACT + n];
                s0[n] += v00 * w0 + v01 * w1v;
                s1[n] += v10 * w0 + v11 * w1v;
            }
        }
        #pragma unroll
        for (int n = 0; n < ACT; n++) {
            s0[n] += __shfl_xor_sync(0xffffffffu, s0[n], 1);
            s0[n] += __shfl_xor_sync(0xffffffffu, s0[n], 2);
            s1[n] += __shfl_xor_sync(0xffffffffu, s1[n], 1);
            s1[n] += __shfl_xor_sync(0xffffffffu, s1[n], 2);
        }
        if (t == 0) {
            const int wn = wid & 3;
            const int rl = warp_m + mt * 16 + g;
            #pragma unroll
            for (int n = 0; n < ACT; n++) {
                Pw[(wn * 128 + rl) * ACT + n]     = s0[n];
                Pw[(wn * 128 + rl + 8) * ACT + n] = s1[n];
            }
        }
    }
    __syncthreads();
    if (tid < 128) {
        #pragma unroll
        for (int n = 0; n < ACT; n++) {
            float s = Pw[(0 * 128 + tid) * ACT + n] + Pw[(1 * 128 + tid) * ACT + n]
                    + Pw[(2 * 128 + tid) * ACT + n] + Pw[(3 * 128 + tid) * ACT + n];
            pb[((size_t)blockIdx.x * BATCH + m0 + tid) * 8 + n] = s;
        }
    }
}

// out[m][n] = relu(b3[n] + sum_bx pb[bx][m][n])
__global__ void combine_out(const float* __restrict__ pb, const float* __restrict__ b3,
                            float* __restrict__ out)
{
    int idx = blockIdx.x * blockDim.x + threadIdx.x;
    if (idx >= BATCH * ACT) return;
    int m = idx / ACT, n = idx % ACT;
    float s = b3[n];
    #pragma unroll
    for (int bx = 0; bx < 4; bx++)
        s += pb[((size_t)bx * BATCH + m) * 8 + n];
    out[(size_t)m * ACT + n] = fmaxf(s, 0.f);
}

// ===================== merged prep kernel =====================
// Flat block-range dispatch over 5 independent elementwise/transpose jobs.
// All jobs use (32,8) blocks with a 32x33 staging tile.
static constexpr int PB0 = 2304;              // gpiB transpose  (48 x 48)
static constexpr int PB1 = PB0 + 2304;        // gpe mask        (48 x 48)
static constexpr int PB2 = PB1 + 2304;        // wx fp32         (48 x 48)
static constexpr int PB3 = PB2 + 768;         // w1 hi/lo split  (48 x 16)
static constexpr int PB4 = PB3 + 256;         // w2 transpose    (16 x 16)

__global__ void prep_all(const float* __restrict__ gpi_w, const float* __restrict__ gpi_mask,
                         const float* __restrict__ gpe_w, const float* __restrict__ gpe_mask,
                         const float* __restrict__ w1, const float* __restrict__ w2,
                         __half* __restrict__ wt_gpiB, __half* __restrict__ wm_gpe,
                         float* __restrict__ wx32, __half* __restrict__ w1s,
                         __half* __restrict__ wt_w2)
{
    __shared__ float tile[32][33];
    const int b  = blockIdx.x;
    const int tx = threadIdx.x, ty = threadIdx.y;

    if (b < PB0) {
        // wt_gpiB[n][k] = f16(gpi_w[1536+k][n] * gpi_mask[n][1536+k]); K=N=1536
        const int k0 = (b % 48) * 32, n0 = (b / 48) * 32;
        const float* w = gpi_w + (size_t)DGPE_IN * DGPI_OUT;
        #pragma unroll
        for (int j = 0; j < 32; j += 8)
            tile[ty + j][tx] = w[(size_t)(k0 + ty + j) * DGPI_OUT + n0 + tx];
        __syncthreads();
        #pragma unroll
        for (int j = 0; j < 32; j += 8) {
            const int n = n0 + ty + j, k = k0 + tx;
            float v = tile[tx][ty + j] * gpi_mask[(size_t)n * DGPI_IN + DGPE_IN + k];
            wt_gpiB[(size_t)n * DGPE_OUT + k] = __float2half_rn(v);
        }
    } else if (b < PB1) {
        // wm_gpe[i][j] = f16(gpe_w[i][j] * gpe_mask[j][i]); I=J... I=1536,J=1536
        const int lb = b - PB0;
        const int j0 = (lb % 48) * 32, i0 = (lb / 48) * 32;
        #pragma unroll
        for (int jj = 0; jj < 32; jj += 8)
            tile[ty + jj][tx] = gpe_mask[(size_t)(j0 + ty + jj) * DGPE_IN + i0 + tx];
        __syncthreads();
        #pragma unroll
        for (int jj = 0; jj < 32; jj += 8) {
            const int i = i0 + ty + jj, j = j0 + tx;
            wm_gpe[(size_t)i * DGPE_OUT + j] =
                __float2half_rn(gpe_w[(size_t)i * DGPE_OUT + j] * tile[tx][ty + jj]);
        }
    } else if (b < PB2) {
        // wx32[i][j] = gpi_w[i][j] * gpi_mask[j][i]  (fp32)
        const int lb = b - PB1;
        const int j0 = (lb % 48) * 32, i0 = (lb / 48) * 32;
        #pragma unroll
        for (int jj = 0; jj < 32; jj += 8)
            tile[ty + jj][tx] = gpi_mask[(size_t)(j0 + ty + jj) * DGPI_IN + i0 + tx];
        __syncthreads();
        #pragma unroll
        for (int jj = 0; jj < 32; jj += 8) {
            const int i = i0 + ty + jj, j = j0 + tx;
            wx32[(size_t)i * DGPI_OUT + j] = gpi_w[(size_t)i * DGPI_OUT + j] * tile[tx][ty + jj];
        }
    } else if (b < PB3) {
        // w1s[n][k]=hi(W1[k][n]), w1s[n][1536+k]=lo; K=1536, N=512
        const int lb = b - PB2;
        const int k0 = (lb % 48) * 32, n0 = (lb / 48) * 32;
        #pragma unroll
        for (int j = 0; j < 32; j += 8)
            tile[ty + j][tx] = w1[(size_t)(k0 + ty + j) * U3 + n0 + tx];
        __syncthreads();
        #pragma unroll
        for (int j = 0; j < 32; j += 8) {
            const int n = n0 + ty + j, k = k0 + tx;
            float v = tile[tx][ty + j];
            __half hi = __float2half_rn(v);
            __half lo = __float2half_rn(v - __half2float(hi));
            w1s[(size_t)n * (2 * DGPI_OUT) + k]            = hi;
            w1s[(size_t)n * (2 * DGPI_OUT) + DGPI_OUT + k] = lo;
        }
    } else {
        // wt_w2[n][k] = f16(w2[k][n]); K=N=512
        const int lb = b - PB3;
        const int k0 = (lb % 16) * 32, n0 = (lb / 16) * 32;
        #pragma unroll
        for (int j = 0; j < 32; j += 8)
            tile[ty + j][tx] = w2[(size_t)(k0 + ty + j) * U3 + n0 + tx];
        __syncthreads();
        #pragma unroll
        for (int j = 0; j < 32; j += 8) {
            const int n = n0 + ty + j, k = k0 + tx;
            wt_w2[(size_t)n * U3 + k] = __float2half_rn(tile[tx][ty + j]);
        }
    }
}

// weffs[i][ hi | hi | lo ] from p0+p1+wx (fp32 sum, deterministic).
__global__ void reduce_split3(const float* __restrict__ p, const float* __restrict__ wx,
                              __half* __restrict__ dst, int J)
{
    const size_t PSTRIDE = (size_t)DGPE_IN * DGPI_OUT;
    const int i = blockIdx.y;
    const int j = (blockIdx.x * blockDim.x + threadIdx.x) * 4;
    const size_t src = (size_t)i * J + j;
    float4 a = *reinterpret_cast<const float4*>(p + src);
    float4 b = *reinterpret_cast<const float4*>(p + PSTRIDE + src);
    float4 c = *reinterpret_cast<const float4*>(wx + src);
    float v0 = a.x + b.x + c.x, v1 = a.y + b.y + c.y;
    float v2 = a.z + b.z + c.z, v3 = a.w + b.w + c.w;
    __half2 h01 = __floats2half2_rn(v0, v1);
    __half2 h23 = __floats2half2_rn(v2, v3);
    __half2 l01 = __floats2half2_rn(v0 - __half2float(h01.x), v1 - __half2float(h01.y));
    __half2 l23 = __floats2half2_rn(v2 - __half2float(h23.x), v3 - __half2float(h23.y));
    const size_t base = (size_t)i * (3 * J);
    *reinterpret_cast<__half2*>(dst + base + j)             = h01;
    *reinterpret_cast<__half2*>(dst + base + j + 2)         = h23;
    *reinterpret_cast<__half2*>(dst + base + J + j)         = h01;
    *reinterpret_cast<__half2*>(dst + base + J + j + 2)     = h23;
    *reinterpret_cast<__half2*>(dst + base + 2 * J + j)     = l01;
    *reinterpret_cast<__half2*>(dst + base + 2 * J + j + 2) = l23;
}

// wfull_h = f16(sum of 3 partials), vectorized; stride = U3*DGPE_IN per partial
__global__ void reduce3q_f16(const float* __restrict__ q, __half* __restrict__ out)
{
    const size_t STRIDE = (size_t)U3 * DGPE_IN;
    int i = (blockIdx.x * blockDim.x + threadIdx.x) * 4;
    float4 s = *reinterpret_cast<const float4*>(q + i);
    #pragma unroll
    for (int z = 1; z < 3; z++) {
        float4 a = *reinterpret_cast<const float4*>(q + z * STRIDE + i);
        s.x += a.x; s.y += a.y; s.z += a.z; s.w += a.w;
    }
    *reinterpret_cast<__half2*>(out + i)     = __floats2half2_rn(s.x, s.y);
    *reinterpret_cast<__half2*>(out + i + 2) = __floats2half2_rn(s.z, s.w);
}

__global__ void bias_eff_kernel(const float* __restrict__ gpi_w, const float* __restrict__ gpi_mask,
                                const float* __restrict__ gpe_b,
                                const float* __restrict__ gpi_b, float* __restrict__ be)
{
    const int n = blockIdx.x * 8 + (threadIdx.x >> 5);
    const int lane = threadIdx.x & 31;
    const float* mrow = gpi_mask + (size_t)n * DGPI_IN + DGPE_IN;
    float s0 = 0.f, s1 = 0.f;
    for (int j = lane; j < DGPE_OUT; j += 64) {
        s0 += gpi_w[(size_t)(DGPE_IN + j) * DGPI_OUT + n] * mrow[j] * gpe_b[j];
        int j2 = j + 32;
        s1 += gpi_w[(size_t)(DGPE_IN + j2) * DGPI_OUT + n] * mrow[j2] * gpe_b[j2];
    }
    float s = s0 + s1;
    #pragma unroll
    for (int off = 16; off; off >>= 1) s += __shfl_xor_sync(0xffffffffu, s, off);
    if (lane == 0) be[n] = gpi_b[n] + s;
}

__global__ void bias_full_kernel(const float* __restrict__ be, const float* __restrict__ w1,
                                 const float* __restrict__ b1, float* __restrict__ bf)
{
    const int n = blockIdx.x * 8 + (threadIdx.x >> 5);
    const int lane = threadIdx.x & 31;
    float s0 = 0.f, s1 = 0.f;
    for (int j = lane; j < DGPI_OUT; j += 64) {
        s0 += be[j] * w1[(size_t)j * U3 + n];
        s1 += be[j + 32] * w1[(size_t)(j + 32) * U3 + n];
    }
    float s = s0 + s1;
    #pragma unroll
    for (int off = 16; off; off >>= 1) s += __shfl_xor_sync(0xffffffffu, s, off);
    if (lane == 0) bf[n] = b1[n] + s;
}

__global__ void convert_f2h(const float* __restrict__ src, __half* __restrict__ dst, int n)
{
    int i = (blockIdx.x * blockDim.x + threadIdx.x) * 4;
    if (i < n) {
        float4 v = *reinterpret_cast<const float4*>(src + i);
        *reinterpret_cast<__half2*>(dst + i)     = __floats2half2_rn(v.x, v.y);
        *reinterpret_cast<__half2*>(dst + i + 2) = __floats2half2_rn(v.z, v.w);
    }
}

// ===================== launch =====================
extern "C" void kernel_launch(void* const* d_in, const int* in_sizes, int n_in,
                              void* d_out, int out_size)
{
    const float* x        = (const float*)d_in[0];
    const float* gpe_mask = (const float*)d_in[1];
    const float* gpe_w    = (const float*)d_in[2];
    const float* gpe_b    = (const float*)d_in[3];
    const float* gpi_mask = (const float*)d_in[4];
    const float* gpi_w    = (const float*)d_in[5];
    const float* gpi_b    = (const float*)d_in[6];
    const float* w1       = (const float*)d_in[7];
    const float* b1       = (const float*)d_in[8];
    const float* w2       = (const float*)d_in[9];
    const float* b2       = (const float*)d_in[10];
    const float* w3       = (const float*)d_in[11];
    const float* b3       = (const float*)d_in[12];
    float* out = (float*)d_out;

    __half *xh, *wt_gpiB, *wm_gpe, *weffs, *w1s, *wfull_h, *wt_w2, *h1;
    float *wx32, *we_p, *wf_q, *bias_eff, *bias_full, *pb;
    cudaGetSymbolAddress((void**)&xh,        g_xh);
    cudaGetSymbolAddress((void**)&wt_gpiB,   g_wt_gpiB);
    cudaGetSymbolAddress((void**)&wm_gpe,    g_wm_gpe);
    cudaGetSymbolAddress((void**)&wx32,      g_wx32);
    cudaGetSymbolAddress((void**)&we_p,      g_we_p);
    cudaGetSymbolAddress((void**)&weffs,     g_weffs);
    cudaGetSymbolAddress((void**)&w1s,       g_w1s);
    cudaGetSymbolAddress((void**)&wf_q,      g_wf_q);
    cudaGetSymbolAddress((void**)&wfull_h,   g_wfull_h);
    cudaGetSymbolAddress((void**)&bias_eff,  g_bias_eff);
    cudaGetSymbolAddress((void**)&bias_full, g_bias_full);
    cudaGetSymbolAddress((void**)&wt_w2,     g_wt_w2);
    cudaGetSymbolAddress((void**)&h1,        g_h1);
    cudaGetSymbolAddress((void**)&pb,        g_pb);

    cudaFuncSetAttribute(gemm_f16,      cudaFuncAttributeMaxDynamicSharedMemorySize, SMEM_TOTAL);
    cudaFuncSetAttribute(gemm_h2_fused, cudaFuncAttributeMaxDynamicSharedMemorySize, SMEM_TOTAL);

    // 3 streams max — proven-safe resource footprint.
    static cudaStream_t sA = nullptr, sB = nullptr, sC = nullptr;
    static cudaEvent_t evRoot, evWfull, evJoin, evH2b;
    if (sA == nullptr) {
        cudaStreamCreateWithFlags(&sA, cudaStreamNonBlocking);
        cudaStreamCreateWithFlags(&sB, cudaStreamNonBlocking);
        cudaStreamCreateWithFlags(&sC, cudaStreamNonBlocking);
        cudaEventCreateWithFlags(&evRoot,  cudaEventDisableTiming);
        cudaEventCreateWithFlags(&evWfull, cudaEventDisableTiming);
        cudaEventCreateWithFlags(&evJoin,  cudaEventDisableTiming);
        cudaEventCreateWithFlags(&evH2b,   cudaEventDisableTiming);
    }

    const dim3 tb(32, 8);
    const int nx = BATCH * DGPE_IN;
    const int KH = DGPE_OUT / 2;   // 768 K-half for W_eff split
    const size_t QSTRIDE = (size_t)U3 * DGPE_IN;
    const size_t PSTRIDE = (size_t)DGPE_IN * DGPI_OUT;
    const int MHALF = BATCH / 2;

    // ---- fork ----
    cudaEventRecord(evRoot, 0);
    cudaStreamWaitEvent(sA, evRoot, 0);
    cudaStreamWaitEvent(sB, evRoot, 0);

    // L: x conversion (big, independent), then off-path bias chain
    convert_f2h<<<(nx / 4 + 255) / 256, 256>>>(x, xh, nx);
    bias_eff_kernel<<<DGPI_OUT / 8, 256>>>(gpi_w, gpi_mask, gpe_b, gpi_b, bias_eff);
    bias_full_kernel<<<U3 / 8, 256>>>(bias_eff, w1, b1, bias_full);

    // sB: SINGLE linear prep chain — no cross-stream edges
    prep_all<<<PB4, tb, 0, sB>>>(gpi_w, gpi_mask, gpe_w, gpe_mask, w1, w2,
                                 wt_gpiB, wm_gpe, wx32, w1s, wt_w2);
    // W_eff split-K merged (grid.z = 2)
    gemm_f16<<<dim3(DGPI_OUT / BN, DGPE_IN / BM, 2), NTHREADS, SMEM_TOTAL, sB>>>(
        wm_gpe, wm_gpe, KH, DGPE_OUT, DGPE_OUT,
        wt_gpiB, DGPE_OUT, nullptr, we_p, 1, DGPI_OUT, KH, 0,
        KH, 0, KH, PSTRIDE);
    reduce_split3<<<dim3(DGPI_OUT / (128 * 4), DGPE_IN), 128, 0, sB>>>(
        we_p, wx32, weffs, DGPI_OUT);
    // W_full merged (grid.z = 3): z0 w1hi x weff_hi, z1 w1lo x weff_hi, z2 w1hi x weff_lo
    gemm_f16<<<dim3(DGPE_IN / BN, U3 / BM, 3), NTHREADS, SMEM_TOTAL, sB>>>(
        w1s, w1s, DGPI_OUT, 2 * DGPI_OUT, 2 * DGPI_OUT,
        weffs, 3 * DGPI_OUT, nullptr, wf_q, 1, DGPE_IN, DGPI_OUT, 0,
        DGPI_OUT, 1, DGPI_OUT, QSTRIDE);
    reduce3q_f16<<<(int)(QSTRIDE / 4 / 256), 256, 0, sB>>>(wf_q, wfull_h);
    cudaEventRecord(evWfull, sB);

    // ---- join + pipelined h1/h2 over batch halves ----
    cudaStreamWaitEvent(0, evWfull, 0);
    cudaEventRecord(evJoin, 0);
    cudaStreamWaitEvent(sA, evJoin, 0);

    // h1a (rows 0..MHALF) on legacy; h1b on sA
    gemm_f16<<<dim3(U3 / BN, MHALF / BM), NTHREADS, SMEM_TOTAL>>>(
        xh, xh, DGPE_IN, DGPE_IN, DGPE_IN,
        wfull_h, DGPE_IN, bias_full, h1, 0, U3, DGPE_IN, 1, 0, 0, 0, 0);
    gemm_f16<<<dim3(U3 / BN, MHALF / BM), NTHREADS, SMEM_TOTAL, sA>>>(
        xh + (size_t)MHALF * DGPE_IN, xh + (size_t)MHALF * DGPE_IN, DGPE_IN, DGPE_IN, DGPE_IN,
        wfull_h, DGPE_IN, bias_full, h1 + (size_t)MHALF * U3, 0, U3, DGPE_IN, 1, 0, 0, 0, 0);

    // h2a behind h1a; h2b behind h1b
    gemm_h2_fused<<<dim3(U3 / BN, MHALF / BM), NTHREADS, SMEM_TOTAL>>>(
        h1, wt_w2, b2, w3, pb);
    gemm_h2_fused<<<dim3(U3 / BN, MHALF / BM), NTHREADS, SMEM_TOTAL, sA>>>(
        h1 + (size_t)MHALF * U3, wt_w2, b2, w3, pb + (size_t)MHALF * 8);
    cudaEventRecord(evH2b, sA);

    // out = relu(sum pb + b3)
    cudaStreamWaitEvent(0, evH2b, 0);
    combine_out<<<(BATCH * ACT + 255) / 256, 256>>>(pb, b3, out);
}